// round 1
// baseline (speedup 1.0000x reference)
#include <cuda_runtime.h>
#include <cuda_bf16.h>
#include <math.h>

#define NMAX 50000
#define DIM  128
#define LNUM 3

// scratch (no allocation allowed)
__device__ float g_agg[(size_t)NMAX * DIM];
__device__ float g_z  [(size_t)NMAX * 2 * DIM];
__device__ float g_h  [(size_t)NMAX * DIM];
__device__ float g_s1[LNUM * 2 * DIM];
__device__ float g_t1[LNUM * 2 * DIM];
__device__ float g_so[(LNUM - 1) * DIM];
__device__ float g_to[(LNUM - 1) * DIM];

// ---------------------------------------------------------------------------
// Precompute BN scale/shift:  s = gamma * rsqrt(var+eps); t = beta - mean*s
// ---------------------------------------------------------------------------
__global__ void bn_pre_kernel(const float* __restrict__ g1, const float* __restrict__ be1,
                              const float* __restrict__ m1, const float* __restrict__ v1,
                              const float* __restrict__ go, const float* __restrict__ bo,
                              const float* __restrict__ mo, const float* __restrict__ vo,
                              float* __restrict__ s1, float* __restrict__ t1,
                              float* __restrict__ so, float* __restrict__ to)
{
    int t = blockIdx.x * blockDim.x + threadIdx.x;
    if (t < LNUM * 2 * DIM) {
        float sc = g1[t] * rsqrtf(v1[t] + 1e-5f);
        s1[t] = sc;
        t1[t] = be1[t] - m1[t] * sc;
    }
    if (t < (LNUM - 1) * DIM) {
        float sc = go[t] * rsqrtf(vo[t] + 1e-5f);
        so[t] = sc;
        to[t] = bo[t] - mo[t] * sc;
    }
}

// ---------------------------------------------------------------------------
// Zero a buffer (float4 granularity)
// ---------------------------------------------------------------------------
__global__ void zero_kernel(float4* __restrict__ p, int n4)
{
    int i = blockIdx.x * blockDim.x + threadIdx.x;
    if (i < n4) p[i] = make_float4(0.f, 0.f, 0.f, 0.f);
}

// ---------------------------------------------------------------------------
// Edge scatter: agg[dst] += h[src].  One warp per edge, float4 per lane.
// ---------------------------------------------------------------------------
__global__ void scatter_kernel(const float* __restrict__ h,
                               const int* __restrict__ src,
                               const int* __restrict__ dst,
                               float* __restrict__ agg, int E)
{
    int w = (blockIdx.x * blockDim.x + threadIdx.x) >> 5;
    int lane = threadIdx.x & 31;
    if (w >= E) return;
    int s = src[w];
    int d = dst[w];
    float4 v = *(const float4*)(h + (size_t)s * DIM + lane * 4);
    float* base = agg + (size_t)d * DIM + lane * 4;
    atomicAdd(base + 0, v.x);
    atomicAdd(base + 1, v.y);
    atomicAdd(base + 2, v.z);
    atomicAdd(base + 3, v.w);
}

// ---------------------------------------------------------------------------
// Fused GEMM: C = act(bn((opt:(1+eps)*Ah + Aagg) @ B + bias))
// BM=BN=128, BK=16, 256 threads, 8x8 per thread.
// ---------------------------------------------------------------------------
#define BM 128
#define BN 128
#define BK 16

__global__ __launch_bounds__(256, 2)
void gemm_fused_kernel(const float* __restrict__ Ah, const float* __restrict__ Aagg,
                       const float* __restrict__ B, const float* __restrict__ bias,
                       const float* __restrict__ bns, const float* __restrict__ bnt,
                       float* __restrict__ C, int M, int K, int Nc,
                       const float* __restrict__ epsp, int layer, int relu)
{
    __shared__ float As[BK][BM];
    __shared__ float Bs[BK][BN];

    int tid = threadIdx.x;
    int tx = tid & 15;       // 0..15 -> col groups of 8
    int ty = tid >> 4;       // 0..15 -> row groups of 8
    int rowBase = blockIdx.y * BM;
    int colBase = blockIdx.x * BN;

    float epsv = 0.f;
    if (Aagg) epsv = 1.0f + epsp[layer];

    float acc[8][8];
#pragma unroll
    for (int i = 0; i < 8; i++)
#pragma unroll
        for (int j = 0; j < 8; j++) acc[i][j] = 0.f;

    int ktiles = K / BK;
    for (int kt = 0; kt < ktiles; kt++) {
        int k0 = kt * BK;
        // ---- load A tile (128x16) transposed into As[k][m] ----
#pragma unroll
        for (int l = 0; l < 2; l++) {
            int f = tid + l * 256;        // 0..511 float4s
            int ar  = f >> 2;             // row in tile 0..127
            int ac4 = f & 3;              // float4 index within 16 k-cols
            int grow = rowBase + ar;
            float4 v = make_float4(0.f, 0.f, 0.f, 0.f);
            if (grow < M) {
                v = *(const float4*)(Ah + (size_t)grow * K + k0 + ac4 * 4);
                if (Aagg) {
                    float4 a = *(const float4*)(Aagg + (size_t)grow * K + k0 + ac4 * 4);
                    v.x = epsv * v.x + a.x;
                    v.y = epsv * v.y + a.y;
                    v.z = epsv * v.z + a.z;
                    v.w = epsv * v.w + a.w;
                }
            }
            As[ac4 * 4 + 0][ar] = v.x;
            As[ac4 * 4 + 1][ar] = v.y;
            As[ac4 * 4 + 2][ar] = v.z;
            As[ac4 * 4 + 3][ar] = v.w;
        }
        // ---- load B tile (16x128) ----
#pragma unroll
        for (int l = 0; l < 2; l++) {
            int f = tid + l * 256;        // 0..511 float4s
            int br  = f >> 5;             // k row 0..15
            int bc4 = f & 31;             // float4 col 0..31
            float4 v = *(const float4*)(B + (size_t)(k0 + br) * Nc + colBase + bc4 * 4);
            *(float4*)&Bs[br][bc4 * 4] = v;
        }
        __syncthreads();

#pragma unroll
        for (int k = 0; k < BK; k++) {
            float a[8], b[8];
            *(float4*)&a[0] = *(const float4*)&As[k][ty * 8];
            *(float4*)&a[4] = *(const float4*)&As[k][ty * 8 + 4];
            *(float4*)&b[0] = *(const float4*)&Bs[k][tx * 8];
            *(float4*)&b[4] = *(const float4*)&Bs[k][tx * 8 + 4];
#pragma unroll
            for (int i = 0; i < 8; i++)
#pragma unroll
                for (int j = 0; j < 8; j++)
                    acc[i][j] = fmaf(a[i], b[j], acc[i][j]);
        }
        __syncthreads();
    }

    // ---- epilogue: bias, optional BN, optional ReLU ----
    int c0 = colBase + tx * 8;
    float bj[8], sj[8], tj[8];
#pragma unroll
    for (int j = 0; j < 8; j++) {
        bj[j] = bias[c0 + j];
        if (bns) { sj[j] = bns[c0 + j]; tj[j] = bnt[c0 + j]; }
    }
#pragma unroll
    for (int i = 0; i < 8; i++) {
        int r = rowBase + ty * 8 + i;
        if (r >= M) break;
        float out[8];
#pragma unroll
        for (int j = 0; j < 8; j++) {
            float v = acc[i][j] + bj[j];
            if (bns) v = fmaf(v, sj[j], tj[j]);
            if (relu) v = fmaxf(v, 0.f);
            out[j] = v;
        }
        *(float4*)(C + (size_t)r * Nc + c0)     = *(float4*)&out[0];
        *(float4*)(C + (size_t)r * Nc + c0 + 4) = *(float4*)&out[4];
    }
}

// ---------------------------------------------------------------------------
// log_softmax over 128 columns, one block per row
// ---------------------------------------------------------------------------
__global__ void logsoftmax_kernel(float* __restrict__ C)
{
    __shared__ float red[DIM];
    int row = blockIdx.x;
    int tid = threadIdx.x;
    float v = C[(size_t)row * DIM + tid];

    red[tid] = v;
    __syncthreads();
    for (int s = DIM / 2; s > 0; s >>= 1) {
        if (tid < s) red[tid] = fmaxf(red[tid], red[tid + s]);
        __syncthreads();
    }
    float m = red[0];
    __syncthreads();

    float e = expf(v - m);
    red[tid] = e;
    __syncthreads();
    for (int s = DIM / 2; s > 0; s >>= 1) {
        if (tid < s) red[tid] += red[tid + s];
        __syncthreads();
    }
    float sum = red[0];

    C[(size_t)row * DIM + tid] = v - m - logf(sum);
}

// ---------------------------------------------------------------------------
extern "C" void kernel_launch(void* const* d_in, const int* in_sizes, int n_in,
                              void* d_out, int out_size)
{
    const float* x    = (const float*)d_in[0];
    const int*   ei   = (const int*)  d_in[1];
    const float* W1   = (const float*)d_in[2];
    const float* b1   = (const float*)d_in[3];
    const float* g1   = (const float*)d_in[4];
    const float* be1  = (const float*)d_in[5];
    const float* m1   = (const float*)d_in[6];
    const float* v1   = (const float*)d_in[7];
    const float* W2   = (const float*)d_in[8];
    const float* b2   = (const float*)d_in[9];
    const float* eps  = (const float*)d_in[10];
    const float* go   = (const float*)d_in[11];
    const float* bo   = (const float*)d_in[12];
    const float* mo   = (const float*)d_in[13];
    const float* vo   = (const float*)d_in[14];

    int N = in_sizes[0] / DIM;
    int E = in_sizes[1] / 2;

    float *agg, *z, *hbuf, *s1, *t1, *so, *to;
    cudaGetSymbolAddress((void**)&agg,  g_agg);
    cudaGetSymbolAddress((void**)&z,    g_z);
    cudaGetSymbolAddress((void**)&hbuf, g_h);
    cudaGetSymbolAddress((void**)&s1,   g_s1);
    cudaGetSymbolAddress((void**)&t1,   g_t1);
    cudaGetSymbolAddress((void**)&so,   g_so);
    cudaGetSymbolAddress((void**)&to,   g_to);

    bn_pre_kernel<<<1, LNUM * 2 * DIM>>>(g1, be1, m1, v1, go, bo, mo, vo, s1, t1, so, to);

    const int* src = ei;
    const int* dst = ei + E;

    const float* h = x;
    for (int i = 0; i < LNUM; i++) {
        int n4 = N * DIM / 4;
        zero_kernel<<<(n4 + 255) / 256, 256>>>((float4*)agg, n4);

        int warps = E;
        scatter_kernel<<<(warps * 32 + 255) / 256, 256>>>(h, src, dst, agg, E);

        // GEMM1: [N,128] @ [128,256] + bias -> BN -> ReLU
        dim3 grid1(2 * DIM / BN, (N + BM - 1) / BM);
        gemm_fused_kernel<<<grid1, 256>>>(h, agg,
                                          W1 + (size_t)i * DIM * 2 * DIM,
                                          b1 + (size_t)i * 2 * DIM,
                                          s1 + (size_t)i * 2 * DIM,
                                          t1 + (size_t)i * 2 * DIM,
                                          z, N, DIM, 2 * DIM, eps, i, 1);

        dim3 grid2(DIM / BN, (N + BM - 1) / BM);
        if (i < LNUM - 1) {
            // GEMM2: [N,256] @ [256,128] + bias -> BN -> ReLU
            gemm_fused_kernel<<<grid2, 256>>>(z, nullptr,
                                              W2 + (size_t)i * 2 * DIM * DIM,
                                              b2 + (size_t)i * DIM,
                                              so + (size_t)i * DIM,
                                              to + (size_t)i * DIM,
                                              hbuf, N, 2 * DIM, DIM, nullptr, 0, 1);
            h = hbuf;
        } else {
            // final GEMM2: bias only, no BN/ReLU, straight to d_out
            gemm_fused_kernel<<<grid2, 256>>>(z, nullptr,
                                              W2 + (size_t)i * 2 * DIM * DIM,
                                              b2 + (size_t)i * DIM,
                                              nullptr, nullptr,
                                              (float*)d_out, N, 2 * DIM, DIM, nullptr, 0, 0);
        }
    }

    logsoftmax_kernel<<<N, DIM>>>((float*)d_out);
}

// round 2
// speedup vs baseline: 1.6054x; 1.6054x over previous
#include <cuda_runtime.h>
#include <cuda_bf16.h>
#include <math.h>

#define NMAX 50000
#define DIM  128
#define LNUM 3

// scratch (no allocation allowed)
__device__ float g_agg[(size_t)NMAX * DIM];
__device__ float g_z  [(size_t)NMAX * 2 * DIM];
__device__ float g_h  [(size_t)NMAX * DIM];
__device__ float g_s1[LNUM * 2 * DIM];
__device__ float g_t1[LNUM * 2 * DIM];
__device__ float g_so[(LNUM - 1) * DIM];
__device__ float g_to[(LNUM - 1) * DIM];

// ---------------------------------------------------------------------------
// packed f32x2 helpers (Blackwell fma.rn.f32x2 — double-rate fp32)
// ---------------------------------------------------------------------------
__device__ __forceinline__ unsigned long long pack2(float x, float y)
{
    unsigned long long r;
    asm("mov.b64 %0, {%1, %2};" : "=l"(r) : "f"(x), "f"(y));
    return r;
}
__device__ __forceinline__ void unpack2(unsigned long long v, float& x, float& y)
{
    asm("mov.b64 {%0, %1}, %2;" : "=f"(x), "=f"(y) : "l"(v));
}
__device__ __forceinline__ void fma2(unsigned long long& d,
                                     unsigned long long a, unsigned long long b)
{
    asm("fma.rn.f32x2 %0, %1, %2, %0;" : "+l"(d) : "l"(a), "l"(b));
}

// ---------------------------------------------------------------------------
// Precompute BN scale/shift:  s = gamma * rsqrt(var+eps); t = beta - mean*s
// ---------------------------------------------------------------------------
__global__ void bn_pre_kernel(const float* __restrict__ g1, const float* __restrict__ be1,
                              const float* __restrict__ m1, const float* __restrict__ v1,
                              const float* __restrict__ go, const float* __restrict__ bo,
                              const float* __restrict__ mo, const float* __restrict__ vo,
                              float* __restrict__ s1, float* __restrict__ t1,
                              float* __restrict__ so, float* __restrict__ to)
{
    int t = blockIdx.x * blockDim.x + threadIdx.x;
    if (t < LNUM * 2 * DIM) {
        float sc = g1[t] * rsqrtf(v1[t] + 1e-5f);
        s1[t] = sc;
        t1[t] = be1[t] - m1[t] * sc;
    }
    if (t < (LNUM - 1) * DIM) {
        float sc = go[t] * rsqrtf(vo[t] + 1e-5f);
        so[t] = sc;
        to[t] = bo[t] - mo[t] * sc;
    }
}

// ---------------------------------------------------------------------------
// Zero a buffer (float4 granularity)
// ---------------------------------------------------------------------------
__global__ void zero_kernel(float4* __restrict__ p, int n4)
{
    int i = blockIdx.x * blockDim.x + threadIdx.x;
    if (i < n4) p[i] = make_float4(0.f, 0.f, 0.f, 0.f);
}

// ---------------------------------------------------------------------------
// Edge scatter: agg[dst] += h[src].  One warp per edge, red.v4 per lane.
// ---------------------------------------------------------------------------
__global__ void scatter_kernel(const float* __restrict__ h,
                               const int* __restrict__ src,
                               const int* __restrict__ dst,
                               float* __restrict__ agg, int E)
{
    int w = (blockIdx.x * blockDim.x + threadIdx.x) >> 5;
    int lane = threadIdx.x & 31;
    if (w >= E) return;
    int s = __ldg(src + w);
    int d = __ldg(dst + w);
    float4 v = __ldg((const float4*)(h + (size_t)s * DIM) + lane);
    float* base = agg + (size_t)d * DIM + lane * 4;
    asm volatile("red.global.add.v4.f32 [%0], {%1, %2, %3, %4};"
                 :: "l"(base), "f"(v.x), "f"(v.y), "f"(v.z), "f"(v.w)
                 : "memory");
}

// ---------------------------------------------------------------------------
// Fused GEMM: C = act(bn((opt:(1+eps)*Ah + Aagg) @ B + bias))
// BM=BN=128, BK=16, 256 threads, 8x8 per thread, packed f32x2 FMAs.
// ---------------------------------------------------------------------------
#define BM 128
#define BN 128
#define BK 16

__global__ __launch_bounds__(256, 2)
void gemm_fused_kernel(const float* __restrict__ Ah, const float* __restrict__ Aagg,
                       const float* __restrict__ B, const float* __restrict__ bias,
                       const float* __restrict__ bns, const float* __restrict__ bnt,
                       float* __restrict__ C, int M, int K, int Nc,
                       const float* __restrict__ epsp, int layer, int relu)
{
    __shared__ float As[BK][BM];
    __shared__ float Bs[BK][BN];

    int tid = threadIdx.x;
    int tx = tid & 15;       // 0..15 -> col groups of 8
    int ty = tid >> 4;       // 0..15 -> row groups of 8
    int rowBase = blockIdx.y * BM;
    int colBase = blockIdx.x * BN;

    float epsv = 0.f;
    if (Aagg) epsv = 1.0f + epsp[layer];

    // acc2[i][j]: packed pair over columns (2j, 2j+1) for row i
    unsigned long long acc2[8][4];
    const unsigned long long z2 = 0ull;  // {0.f, 0.f}
#pragma unroll
    for (int i = 0; i < 8; i++)
#pragma unroll
        for (int j = 0; j < 4; j++) acc2[i][j] = z2;

    int ktiles = K / BK;
    for (int kt = 0; kt < ktiles; kt++) {
        int k0 = kt * BK;
        // ---- load A tile (128x16) transposed into As[k][m] ----
#pragma unroll
        for (int l = 0; l < 2; l++) {
            int f = tid + l * 256;        // 0..511 float4s
            int ar  = f >> 2;             // row in tile 0..127
            int ac4 = f & 3;              // float4 index within 16 k-cols
            int grow = rowBase + ar;
            float4 v = make_float4(0.f, 0.f, 0.f, 0.f);
            if (grow < M) {
                v = *(const float4*)(Ah + (size_t)grow * K + k0 + ac4 * 4);
                if (Aagg) {
                    float4 a = *(const float4*)(Aagg + (size_t)grow * K + k0 + ac4 * 4);
                    v.x = fmaf(epsv, v.x, a.x);
                    v.y = fmaf(epsv, v.y, a.y);
                    v.z = fmaf(epsv, v.z, a.z);
                    v.w = fmaf(epsv, v.w, a.w);
                }
            }
            As[ac4 * 4 + 0][ar] = v.x;
            As[ac4 * 4 + 1][ar] = v.y;
            As[ac4 * 4 + 2][ar] = v.z;
            As[ac4 * 4 + 3][ar] = v.w;
        }
        // ---- load B tile (16x128) ----
#pragma unroll
        for (int l = 0; l < 2; l++) {
            int f = tid + l * 256;        // 0..511 float4s
            int br  = f >> 5;             // k row 0..15
            int bc4 = f & 31;             // float4 col 0..31
            float4 v = *(const float4*)(B + (size_t)(k0 + br) * Nc + colBase + bc4 * 4);
            *(float4*)&Bs[br][bc4 * 4] = v;
        }
        __syncthreads();

#pragma unroll
        for (int k = 0; k < BK; k++) {
            float a[8];
            *(float4*)&a[0] = *(const float4*)&As[k][ty * 8];
            *(float4*)&a[4] = *(const float4*)&As[k][ty * 8 + 4];
            unsigned long long b2[4];
            *(ulonglong2*)&b2[0] = *(const ulonglong2*)&Bs[k][tx * 8];
            *(ulonglong2*)&b2[2] = *(const ulonglong2*)&Bs[k][tx * 8 + 4];
#pragma unroll
            for (int i = 0; i < 8; i++) {
                unsigned long long a2 = pack2(a[i], a[i]);
#pragma unroll
                for (int j = 0; j < 4; j++)
                    fma2(acc2[i][j], a2, b2[j]);
            }
        }
        __syncthreads();
    }

    // ---- epilogue: bias, optional BN, optional ReLU ----
    int c0 = colBase + tx * 8;
    float bj[8], sj[8], tj[8];
#pragma unroll
    for (int j = 0; j < 8; j++) {
        bj[j] = bias[c0 + j];
        if (bns) { sj[j] = bns[c0 + j]; tj[j] = bnt[c0 + j]; }
    }
#pragma unroll
    for (int i = 0; i < 8; i++) {
        int r = rowBase + ty * 8 + i;
        if (r >= M) break;
        float out[8];
#pragma unroll
        for (int j = 0; j < 4; j++)
            unpack2(acc2[i][j], out[2 * j], out[2 * j + 1]);
#pragma unroll
        for (int j = 0; j < 8; j++) {
            float v = out[j] + bj[j];
            if (bns) v = fmaf(v, sj[j], tj[j]);
            if (relu) v = fmaxf(v, 0.f);
            out[j] = v;
        }
        *(float4*)(C + (size_t)r * Nc + c0)     = *(float4*)&out[0];
        *(float4*)(C + (size_t)r * Nc + c0 + 4) = *(float4*)&out[4];
    }
}

// ---------------------------------------------------------------------------
// log_softmax over 128 columns, one block per row
// ---------------------------------------------------------------------------
__global__ void logsoftmax_kernel(float* __restrict__ C)
{
    __shared__ float red[DIM];
    int row = blockIdx.x;
    int tid = threadIdx.x;
    float v = C[(size_t)row * DIM + tid];

    red[tid] = v;
    __syncthreads();
    for (int s = DIM / 2; s > 0; s >>= 1) {
        if (tid < s) red[tid] = fmaxf(red[tid], red[tid + s]);
        __syncthreads();
    }
    float m = red[0];
    __syncthreads();

    float e = expf(v - m);
    red[tid] = e;
    __syncthreads();
    for (int s = DIM / 2; s > 0; s >>= 1) {
        if (tid < s) red[tid] += red[tid + s];
        __syncthreads();
    }
    float sum = red[0];

    C[(size_t)row * DIM + tid] = v - m - logf(sum);
}

// ---------------------------------------------------------------------------
extern "C" void kernel_launch(void* const* d_in, const int* in_sizes, int n_in,
                              void* d_out, int out_size)
{
    const float* x    = (const float*)d_in[0];
    const int*   ei   = (const int*)  d_in[1];
    const float* W1   = (const float*)d_in[2];
    const float* b1   = (const float*)d_in[3];
    const float* g1   = (const float*)d_in[4];
    const float* be1  = (const float*)d_in[5];
    const float* m1   = (const float*)d_in[6];
    const float* v1   = (const float*)d_in[7];
    const float* W2   = (const float*)d_in[8];
    const float* b2   = (const float*)d_in[9];
    const float* eps  = (const float*)d_in[10];
    const float* go   = (const float*)d_in[11];
    const float* bo   = (const float*)d_in[12];
    const float* mo   = (const float*)d_in[13];
    const float* vo   = (const float*)d_in[14];

    int N = in_sizes[0] / DIM;
    int E = in_sizes[1] / 2;

    float *agg, *z, *hbuf, *s1, *t1, *so, *to;
    cudaGetSymbolAddress((void**)&agg,  g_agg);
    cudaGetSymbolAddress((void**)&z,    g_z);
    cudaGetSymbolAddress((void**)&hbuf, g_h);
    cudaGetSymbolAddress((void**)&s1,   g_s1);
    cudaGetSymbolAddress((void**)&t1,   g_t1);
    cudaGetSymbolAddress((void**)&so,   g_so);
    cudaGetSymbolAddress((void**)&to,   g_to);

    bn_pre_kernel<<<1, LNUM * 2 * DIM>>>(g1, be1, m1, v1, go, bo, mo, vo, s1, t1, so, to);

    const int* src = ei;
    const int* dst = ei + E;

    const float* h = x;
    for (int i = 0; i < LNUM; i++) {
        int n4 = N * DIM / 4;
        zero_kernel<<<(n4 + 255) / 256, 256>>>((float4*)agg, n4);

        scatter_kernel<<<(E * 32 + 255) / 256, 256>>>(h, src, dst, agg, E);

        // GEMM1: [N,128] @ [128,256] + bias -> BN -> ReLU
        dim3 grid1(2 * DIM / BN, (N + BM - 1) / BM);
        gemm_fused_kernel<<<grid1, 256>>>(h, agg,
                                          W1 + (size_t)i * DIM * 2 * DIM,
                                          b1 + (size_t)i * 2 * DIM,
                                          s1 + (size_t)i * 2 * DIM,
                                          t1 + (size_t)i * 2 * DIM,
                                          z, N, DIM, 2 * DIM, eps, i, 1);

        dim3 grid2(DIM / BN, (N + BM - 1) / BM);
        if (i < LNUM - 1) {
            // GEMM2: [N,256] @ [256,128] + bias -> BN -> ReLU
            gemm_fused_kernel<<<grid2, 256>>>(z, nullptr,
                                              W2 + (size_t)i * 2 * DIM * DIM,
                                              b2 + (size_t)i * DIM,
                                              so + (size_t)i * DIM,
                                              to + (size_t)i * DIM,
                                              hbuf, N, 2 * DIM, DIM, nullptr, 0, 1);
            h = hbuf;
        } else {
            // final GEMM2: bias only, no BN/ReLU, straight to d_out
            gemm_fused_kernel<<<grid2, 256>>>(z, nullptr,
                                              W2 + (size_t)i * 2 * DIM * DIM,
                                              b2 + (size_t)i * DIM,
                                              nullptr, nullptr,
                                              (float*)d_out, N, 2 * DIM, DIM, nullptr, 0, 0);
        }
    }

    logsoftmax_kernel<<<N, DIM>>>((float*)d_out);
}

// round 4
// speedup vs baseline: 1.7649x; 1.0993x over previous
#include <cuda_runtime.h>
#include <cuda_bf16.h>
#include <cstdint>
#include <math.h>

#define NMAX 50000
#define DIM  128
#define LNUM 3

// ---------------------------------------------------------------------------
// scratch (no allocation allowed)
// ---------------------------------------------------------------------------
__device__ float g_agg[(size_t)NMAX * DIM];
__device__ float g_z  [(size_t)NMAX * 2 * DIM];
__device__ float g_h  [(size_t)NMAX * DIM];
__device__ float g_s1[LNUM * 2 * DIM];
__device__ float g_t1[LNUM * 2 * DIM];
__device__ float g_so[(LNUM - 1) * DIM];
__device__ float g_to[(LNUM - 1) * DIM];
// transposed + bf16-split weights: W1T [L][256][128], W2T [L][128][256]
__device__ __nv_bfloat16 g_w1hi[LNUM * 2 * DIM * DIM];
__device__ __nv_bfloat16 g_w1lo[LNUM * 2 * DIM * DIM];
__device__ __nv_bfloat16 g_w2hi[LNUM * 2 * DIM * DIM];
__device__ __nv_bfloat16 g_w2lo[LNUM * 2 * DIM * DIM];

// ---------------------------------------------------------------------------
// helpers
// ---------------------------------------------------------------------------
__device__ __forceinline__ uint32_t smem_to_u32(const void* p) {
    uint32_t a;
    asm("{ .reg .u64 t; cvta.to.shared.u64 t, %1; cvt.u32.u64 %0, t; }" : "=r"(a) : "l"(p));
    return a;
}

__device__ __forceinline__ void ldmx4(uint32_t* r, uint32_t addr) {
    asm volatile("ldmatrix.sync.aligned.m8n8.x4.shared.b16 {%0,%1,%2,%3}, [%4];"
                 : "=r"(r[0]), "=r"(r[1]), "=r"(r[2]), "=r"(r[3]) : "r"(addr));
}

__device__ __forceinline__ void mma_bf16(float* c, const uint32_t* a, uint32_t b0, uint32_t b1) {
    asm volatile("mma.sync.aligned.m16n8k16.row.col.f32.bf16.bf16.f32 "
                 "{%0,%1,%2,%3}, {%4,%5,%6,%7}, {%8,%9}, {%0,%1,%2,%3};"
                 : "+f"(c[0]), "+f"(c[1]), "+f"(c[2]), "+f"(c[3])
                 : "r"(a[0]), "r"(a[1]), "r"(a[2]), "r"(a[3]), "r"(b0), "r"(b1));
}

// split two floats into packed bf16 hi pair + bf16 lo (residual) pair
__device__ __forceinline__ void split2(float a, float b, uint32_t& hi, uint32_t& lo) {
    __nv_bfloat16 ha = __float2bfloat16_rn(a);
    __nv_bfloat16 hb = __float2bfloat16_rn(b);
    float ra = a - __bfloat162float(ha);
    float rb = b - __bfloat162float(hb);
    __nv_bfloat162 H; H.x = ha; H.y = hb;
    __nv_bfloat162 L = __floats2bfloat162_rn(ra, rb);
    hi = *(uint32_t*)&H;
    lo = *(uint32_t*)&L;
}

// ---------------------------------------------------------------------------
// BN precompute
// ---------------------------------------------------------------------------
__global__ void bn_pre_kernel(const float* __restrict__ g1, const float* __restrict__ be1,
                              const float* __restrict__ m1, const float* __restrict__ v1,
                              const float* __restrict__ go, const float* __restrict__ bo,
                              const float* __restrict__ mo, const float* __restrict__ vo,
                              float* __restrict__ s1, float* __restrict__ t1,
                              float* __restrict__ so, float* __restrict__ to)
{
    int t = blockIdx.x * blockDim.x + threadIdx.x;
    if (t < LNUM * 2 * DIM) {
        float sc = g1[t] * rsqrtf(v1[t] + 1e-5f);
        s1[t] = sc;
        t1[t] = be1[t] - m1[t] * sc;
    }
    if (t < (LNUM - 1) * DIM) {
        float sc = go[t] * rsqrtf(vo[t] + 1e-5f);
        so[t] = sc;
        to[t] = bo[t] - mo[t] * sc;
    }
}

// ---------------------------------------------------------------------------
// Weight transpose + bf16 hi/lo split.
// W1 [l][k=128][n=256] -> W1T [l][n][k];  W2 [l][k=256][n=128] -> W2T [l][n][k]
// ---------------------------------------------------------------------------
__global__ void wsplit_kernel(const float* __restrict__ W1, const float* __restrict__ W2,
                              __nv_bfloat16* __restrict__ w1h, __nv_bfloat16* __restrict__ w1l,
                              __nv_bfloat16* __restrict__ w2h, __nv_bfloat16* __restrict__ w2l)
{
    int idx = blockIdx.x * blockDim.x + threadIdx.x;
    const int tot = LNUM * 2 * DIM * DIM;
    if (idx >= tot) return;
    int l = idx / (2 * DIM * DIM);
    int rem = idx % (2 * DIM * DIM);
    {
        int n = rem / DIM, k = rem % DIM;     // W1T[n=0..255][k=0..127]
        float w = W1[(size_t)l * DIM * 2 * DIM + (size_t)k * 2 * DIM + n];
        __nv_bfloat16 h = __float2bfloat16_rn(w);
        w1h[idx] = h;
        w1l[idx] = __float2bfloat16_rn(w - __bfloat162float(h));
    }
    {
        int n2 = rem / (2 * DIM), k2 = rem % (2 * DIM);  // W2T[n=0..127][k=0..255]
        float w = W2[(size_t)l * 2 * DIM * DIM + (size_t)k2 * DIM + n2];
        __nv_bfloat16 h = __float2bfloat16_rn(w);
        w2h[idx] = h;
        w2l[idx] = __float2bfloat16_rn(w - __bfloat162float(h));
    }
}

// ---------------------------------------------------------------------------
// Zero buffer
// ---------------------------------------------------------------------------
__global__ void zero_kernel(float4* __restrict__ p, int n4)
{
    int i = blockIdx.x * blockDim.x + threadIdx.x;
    if (i < n4) p[i] = make_float4(0.f, 0.f, 0.f, 0.f);
}

// ---------------------------------------------------------------------------
// Edge scatter: agg[dst] += h[src].  One warp per edge, red.v4 per lane.
// ---------------------------------------------------------------------------
__global__ void scatter_kernel(const float* __restrict__ h,
                               const int* __restrict__ src,
                               const int* __restrict__ dst,
                               float* __restrict__ agg, int E)
{
    int w = (blockIdx.x * blockDim.x + threadIdx.x) >> 5;
    int lane = threadIdx.x & 31;
    if (w >= E) return;
    int s = __ldg(src + w);
    int d = __ldg(dst + w);
    float4 v = __ldg((const float4*)(h + (size_t)s * DIM) + lane);
    float* base = agg + (size_t)d * DIM + lane * 4;
    asm volatile("red.global.add.v4.f32 [%0], {%1, %2, %3, %4};"
                 :: "l"(base), "f"(v.x), "f"(v.y), "f"(v.z), "f"(v.w)
                 : "memory");
}

// ---------------------------------------------------------------------------
// 3xBF16 mma.sync GEMM: C = act(bn(((1+eps)Ah + Aagg) @ W + bias))
//   block 128x128, 8 warps (2M x 4N), warp tile 64x32, BK=32 double-buffered.
//   W provided pre-transposed [n][K] bf16 hi/lo.
// ---------------------------------------------------------------------------
#define BK 32
#define ASTRIDE 40                 // bf16 elems per smem row (80 B, conflict-free)
#define ABUF_B (128 * ASTRIDE * 2) // 10240 B per buffer
#define STAGE_B (4 * ABUF_B)       // Ahi,Alo,Whi,Wlo

__global__ __launch_bounds__(256)
void gemm_mma_kernel(const float* __restrict__ Ah, const float* __restrict__ Aagg,
                     const __nv_bfloat16* __restrict__ Whi, const __nv_bfloat16* __restrict__ Wlo,
                     const float* __restrict__ bias, const float* __restrict__ bns,
                     const float* __restrict__ bnt, float* __restrict__ C,
                     int M, int K, int Nc, const float* __restrict__ epsp, int relu)
{
    extern __shared__ char smem[];
    const int tid = threadIdx.x;
    const int lane = tid & 31, wid = tid >> 5;
    const int warpM = wid >> 2, warpN = wid & 3;
    const int rowBase = blockIdx.y * 128;
    const int colBase = blockIdx.x * 128;
    const uint32_t sbase = smem_to_u32(smem);

    float epsv = Aagg ? (1.0f + epsp[0]) : 0.f;

    float acc[4][4][4];
#pragma unroll
    for (int a = 0; a < 4; a++)
#pragma unroll
        for (int b = 0; b < 4; b++)
#pragma unroll
            for (int c = 0; c < 4; c++) acc[a][b][c] = 0.f;

    // ldmatrix per-lane offsets (bytes, relative to buffer base)
    const int frow = lane & 15, fk = (lane >> 4) * 8;
    uint32_t offA[4], offB[2];
#pragma unroll
    for (int mf = 0; mf < 4; mf++)
        offA[mf] = ((warpM * 64 + mf * 16 + frow) * ASTRIDE + fk) * 2;
#pragma unroll
    for (int nb = 0; nb < 2; nb++)
        offB[nb] = ((warpN * 32 + nb * 16 + frow) * ASTRIDE + fk) * 2;

    const int nch = K / BK;

    // register prefetch buffers
    float4 pa[4];
    uint64_t pwh[4], pwl[4];

    // ---- prefetch chunk 0 ----
    {
        int k0 = 0;
#pragma unroll
        for (int i = 0; i < 4; i++) {
            int f = tid + i * 256;
            int r = f >> 3, q = f & 7;
            int g = rowBase + r;
            float4 v = make_float4(0.f, 0.f, 0.f, 0.f);
            if (g < M) {
                v = *(const float4*)(Ah + (size_t)g * K + k0 + q * 4);
                if (Aagg) {
                    float4 a = *(const float4*)(Aagg + (size_t)g * K + k0 + q * 4);
                    v.x = fmaf(epsv, v.x, a.x);
                    v.y = fmaf(epsv, v.y, a.y);
                    v.z = fmaf(epsv, v.z, a.z);
                    v.w = fmaf(epsv, v.w, a.w);
                }
            }
            pa[i] = v;
            const uint64_t* wh = (const uint64_t*)(Whi + (size_t)(colBase + r) * K + k0);
            const uint64_t* wl = (const uint64_t*)(Wlo + (size_t)(colBase + r) * K + k0);
            pwh[i] = __ldg(wh + q);
            pwl[i] = __ldg(wl + q);
        }
    }

    int s = 0;
    for (int c = 0; c < nch; c++) {
        // ---- convert + store prefetched regs into stage s ----
        {
            char* Ahi_s = smem + s * STAGE_B;
            char* Alo_s = Ahi_s + ABUF_B;
            char* Whi_s = Ahi_s + 2 * ABUF_B;
            char* Wlo_s = Ahi_s + 3 * ABUF_B;
#pragma unroll
            for (int i = 0; i < 4; i++) {
                int f = tid + i * 256;
                int r = f >> 3, q = f & 7;
                int so = r * (ASTRIDE * 2) + q * 8;
                uint32_t h01, l01, h23, l23;
                split2(pa[i].x, pa[i].y, h01, l01);
                split2(pa[i].z, pa[i].w, h23, l23);
                *(uint2*)(Ahi_s + so) = make_uint2(h01, h23);
                *(uint2*)(Alo_s + so) = make_uint2(l01, l23);
                *(uint64_t*)(Whi_s + so) = pwh[i];
                *(uint64_t*)(Wlo_s + so) = pwl[i];
            }
        }
        __syncthreads();

        // ---- prefetch next chunk (overlaps with mma below) ----
        if (c + 1 < nch) {
            int k0 = (c + 1) * BK;
#pragma unroll
            for (int i = 0; i < 4; i++) {
                int f = tid + i * 256;
                int r = f >> 3, q = f & 7;
                int g = rowBase + r;
                float4 v = make_float4(0.f, 0.f, 0.f, 0.f);
                if (g < M) {
                    v = *(const float4*)(Ah + (size_t)g * K + k0 + q * 4);
                    if (Aagg) {
                        float4 a = *(const float4*)(Aagg + (size_t)g * K + k0 + q * 4);
                        v.x = fmaf(epsv, v.x, a.x);
                        v.y = fmaf(epsv, v.y, a.y);
                        v.z = fmaf(epsv, v.z, a.z);
                        v.w = fmaf(epsv, v.w, a.w);
                    }
                }
                pa[i] = v;
                const uint64_t* wh = (const uint64_t*)(Whi + (size_t)(colBase + r) * K + k0);
                const uint64_t* wl = (const uint64_t*)(Wlo + (size_t)(colBase + r) * K + k0);
                pwh[i] = __ldg(wh + q);
                pwl[i] = __ldg(wl + q);
            }
        }

        // ---- mma over stage s: 2 k16 steps ----
        uint32_t bufA_hi = sbase + s * STAGE_B;
        uint32_t bufA_lo = bufA_hi + ABUF_B;
        uint32_t bufW_hi = bufA_hi + 2 * ABUF_B;
        uint32_t bufW_lo = bufA_hi + 3 * ABUF_B;
#pragma unroll
        for (int ks = 0; ks < 2; ks++) {
            uint32_t ah[4][4], al[4][4], bh[2][4], bl[2][4];
#pragma unroll
            for (int mf = 0; mf < 4; mf++) {
                ldmx4(ah[mf], bufA_hi + offA[mf] + ks * 32);
                ldmx4(al[mf], bufA_lo + offA[mf] + ks * 32);
            }
#pragma unroll
            for (int nb = 0; nb < 2; nb++) {
                ldmx4(bh[nb], bufW_hi + offB[nb] + ks * 32);
                ldmx4(bl[nb], bufW_lo + offB[nb] + ks * 32);
            }
#pragma unroll
            for (int mf = 0; mf < 4; mf++) {
#pragma unroll
                for (int nf = 0; nf < 4; nf++) {
                    int nb = nf >> 1, sel = nf & 1;
                    uint32_t b0h = bh[nb][sel], b1h = bh[nb][sel + 2];
                    uint32_t b0l = bl[nb][sel], b1l = bl[nb][sel + 2];
                    mma_bf16(acc[mf][nf], ah[mf], b0h, b1h);
                    mma_bf16(acc[mf][nf], ah[mf], b0l, b1l);
                    mma_bf16(acc[mf][nf], al[mf], b0h, b1h);
                }
            }
        }
        __syncthreads();
        s ^= 1;
    }

    // ---- epilogue ----
    const int g = lane >> 2, tig = lane & 3;
    float bj0[4], bj1[4], sj0[4], sj1[4], tj0[4], tj1[4];
#pragma unroll
    for (int nf = 0; nf < 4; nf++) {
        int col = colBase + warpN * 32 + nf * 8 + 2 * tig;
        bj0[nf] = bias[col];
        bj1[nf] = bias[col + 1];
        if (bns) {
            sj0[nf] = bns[col];  sj1[nf] = bns[col + 1];
            tj0[nf] = bnt[col];  tj1[nf] = bnt[col + 1];
        }
    }
#pragma unroll
    for (int mf = 0; mf < 4; mf++) {
#pragma unroll
        for (int half = 0; half < 2; half++) {
            int row = rowBase + warpM * 64 + mf * 16 + g + half * 8;
            if (row >= M) continue;
#pragma unroll
            for (int nf = 0; nf < 4; nf++) {
                int col = colBase + warpN * 32 + nf * 8 + 2 * tig;
                float v0 = acc[mf][nf][half * 2 + 0] + bj0[nf];
                float v1 = acc[mf][nf][half * 2 + 1] + bj1[nf];
                if (bns) {
                    v0 = fmaf(v0, sj0[nf], tj0[nf]);
                    v1 = fmaf(v1, sj1[nf], tj1[nf]);
                }
                if (relu) { v0 = fmaxf(v0, 0.f); v1 = fmaxf(v1, 0.f); }
                float2 o = make_float2(v0, v1);
                *(float2*)(C + (size_t)row * Nc + col) = o;
            }
        }
    }
}

// ---------------------------------------------------------------------------
// log_softmax over 128 columns, one block per row
// ---------------------------------------------------------------------------
__global__ void logsoftmax_kernel(float* __restrict__ C)
{
    __shared__ float red[DIM];
    int row = blockIdx.x;
    int tid = threadIdx.x;
    float v = C[(size_t)row * DIM + tid];

    red[tid] = v;
    __syncthreads();
    for (int s = DIM / 2; s > 0; s >>= 1) {
        if (tid < s) red[tid] = fmaxf(red[tid], red[tid + s]);
        __syncthreads();
    }
    float m = red[0];
    __syncthreads();

    float e = expf(v - m);
    red[tid] = e;
    __syncthreads();
    for (int s = DIM / 2; s > 0; s >>= 1) {
        if (tid < s) red[tid] += red[tid + s];
        __syncthreads();
    }
    float sum = red[0];

    C[(size_t)row * DIM + tid] = v - m - logf(sum);
}

// ---------------------------------------------------------------------------
extern "C" void kernel_launch(void* const* d_in, const int* in_sizes, int n_in,
                              void* d_out, int out_size)
{
    const float* x    = (const float*)d_in[0];
    const int*   ei   = (const int*)  d_in[1];
    const float* W1   = (const float*)d_in[2];
    const float* b1   = (const float*)d_in[3];
    const float* g1   = (const float*)d_in[4];
    const float* be1  = (const float*)d_in[5];
    const float* m1   = (const float*)d_in[6];
    const float* v1   = (const float*)d_in[7];
    const float* W2   = (const float*)d_in[8];
    const float* b2   = (const float*)d_in[9];
    const float* eps  = (const float*)d_in[10];
    const float* go   = (const float*)d_in[11];
    const float* bo   = (const float*)d_in[12];
    const float* mo   = (const float*)d_in[13];
    const float* vo   = (const float*)d_in[14];

    int N = in_sizes[0] / DIM;
    int E = in_sizes[1] / 2;

    float *agg, *z, *hbuf, *s1, *t1, *so, *to;
    __nv_bfloat16 *w1h, *w1l, *w2h, *w2l;
    cudaGetSymbolAddress((void**)&agg,  g_agg);
    cudaGetSymbolAddress((void**)&z,    g_z);
    cudaGetSymbolAddress((void**)&hbuf, g_h);
    cudaGetSymbolAddress((void**)&s1,   g_s1);
    cudaGetSymbolAddress((void**)&t1,   g_t1);
    cudaGetSymbolAddress((void**)&so,   g_so);
    cudaGetSymbolAddress((void**)&to,   g_to);
    cudaGetSymbolAddress((void**)&w1h,  g_w1hi);
    cudaGetSymbolAddress((void**)&w1l,  g_w1lo);
    cudaGetSymbolAddress((void**)&w2h,  g_w2hi);
    cudaGetSymbolAddress((void**)&w2l,  g_w2lo);

    const int dynSmem = 2 * STAGE_B;  // 81920 B
    cudaFuncSetAttribute(gemm_mma_kernel, cudaFuncAttributeMaxDynamicSharedMemorySize, dynSmem);

    bn_pre_kernel<<<1, LNUM * 2 * DIM>>>(g1, be1, m1, v1, go, bo, mo, vo, s1, t1, so, to);
    {
        int tot = LNUM * 2 * DIM * DIM;
        wsplit_kernel<<<(tot + 255) / 256, 256>>>(W1, W2, w1h, w1l, w2h, w2l);
    }

    const int* src = ei;
    const int* dst = ei + E;
    int mblocks = (N + 127) / 128;

    const float* h = x;
    for (int i = 0; i < LNUM; i++) {
        int n4 = N * DIM / 4;
        zero_kernel<<<(n4 + 255) / 256, 256>>>((float4*)agg, n4);
        scatter_kernel<<<(E * 32 + 255) / 256, 256>>>(h, src, dst, agg, E);

        // GEMM1: z[N,256] = ((1+eps)h + agg) @ W1 -> bias, BN, ReLU
        dim3 grid1(2, mblocks);
        gemm_mma_kernel<<<grid1, 256, dynSmem>>>(h, agg,
                                                 w1h + (size_t)i * 2 * DIM * DIM,
                                                 w1l + (size_t)i * 2 * DIM * DIM,
                                                 b1 + (size_t)i * 2 * DIM,
                                                 s1 + (size_t)i * 2 * DIM,
                                                 t1 + (size_t)i * 2 * DIM,
                                                 z, N, DIM, 2 * DIM, eps + i, 1);

        dim3 grid2(1, mblocks);
        if (i < LNUM - 1) {
            gemm_mma_kernel<<<grid2, 256, dynSmem>>>(z, nullptr,
                                                     w2h + (size_t)i * 2 * DIM * DIM,
                                                     w2l + (size_t)i * 2 * DIM * DIM,
                                                     b2 + (size_t)i * DIM,
                                                     so + (size_t)i * DIM,
                                                     to + (size_t)i * DIM,
                                                     hbuf, N, 2 * DIM, DIM, nullptr, 1);
            h = hbuf;
        } else {
            gemm_mma_kernel<<<grid2, 256, dynSmem>>>(z, nullptr,
                                                     w2h + (size_t)i * 2 * DIM * DIM,
                                                     w2l + (size_t)i * 2 * DIM * DIM,
                                                     b2 + (size_t)i * DIM,
                                                     nullptr, nullptr,
                                                     (float*)d_out, N, 2 * DIM, DIM, nullptr, 0);
        }
    }

    logsoftmax_kernel<<<N, DIM>>>((float*)d_out);
}

// round 5
// speedup vs baseline: 2.7588x; 1.5632x over previous
#include <cuda_runtime.h>
#include <cuda_bf16.h>
#include <cstdint>
#include <math.h>

#define NMAX 50000
#define EMAX 800000
#define DIM  128
#define LNUM 3

// ---------------------------------------------------------------------------
// scratch (no allocation allowed)
// ---------------------------------------------------------------------------
__device__ float g_h  [(size_t)NMAX * DIM];                 // fp32 activations between layers
__device__ __nv_bfloat16 g_chi[(size_t)NMAX * DIM];         // combine hi (GEMM1 input)
__device__ __nv_bfloat16 g_clo[(size_t)NMAX * DIM];         // combine lo
__device__ __nv_bfloat16 g_zhi[(size_t)NMAX * 2 * DIM];     // z hi (GEMM2 input)
__device__ __nv_bfloat16 g_zlo[(size_t)NMAX * 2 * DIM];     // z lo
__device__ float g_s1[LNUM * 2 * DIM];
__device__ float g_t1[LNUM * 2 * DIM];
__device__ float g_so[(LNUM - 1) * DIM];
__device__ float g_to[(LNUM - 1) * DIM];
// transposed + bf16-split weights: W1T [L][256][128], W2T [L][128][256]
__device__ __nv_bfloat16 g_w1hi[LNUM * 2 * DIM * DIM];
__device__ __nv_bfloat16 g_w1lo[LNUM * 2 * DIM * DIM];
__device__ __nv_bfloat16 g_w2hi[LNUM * 2 * DIM * DIM];
__device__ __nv_bfloat16 g_w2lo[LNUM * 2 * DIM * DIM];
// CSR
__device__ int g_rowptr[NMAX + 1];
__device__ int g_cursor[NMAX];
__device__ int g_adj[EMAX];

// ---------------------------------------------------------------------------
// helpers
// ---------------------------------------------------------------------------
__device__ __forceinline__ uint32_t smem_to_u32(const void* p) {
    uint32_t a;
    asm("{ .reg .u64 t; cvta.to.shared.u64 t, %1; cvt.u32.u64 %0, t; }" : "=r"(a) : "l"(p));
    return a;
}
__device__ __forceinline__ void ldmx4(uint32_t* r, uint32_t addr) {
    asm volatile("ldmatrix.sync.aligned.m8n8.x4.shared.b16 {%0,%1,%2,%3}, [%4];"
                 : "=r"(r[0]), "=r"(r[1]), "=r"(r[2]), "=r"(r[3]) : "r"(addr));
}
__device__ __forceinline__ void mma_bf16(float* c, const uint32_t* a, uint32_t b0, uint32_t b1) {
    asm volatile("mma.sync.aligned.m16n8k16.row.col.f32.bf16.bf16.f32 "
                 "{%0,%1,%2,%3}, {%4,%5,%6,%7}, {%8,%9}, {%0,%1,%2,%3};"
                 : "+f"(c[0]), "+f"(c[1]), "+f"(c[2]), "+f"(c[3])
                 : "r"(a[0]), "r"(a[1]), "r"(a[2]), "r"(a[3]), "r"(b0), "r"(b1));
}
// split two floats into packed bf16 hi pair + bf16 lo (residual) pair
__device__ __forceinline__ void split2(float a, float b, uint32_t& hi, uint32_t& lo) {
    __nv_bfloat16 ha = __float2bfloat16_rn(a);
    __nv_bfloat16 hb = __float2bfloat16_rn(b);
    float ra = a - __bfloat162float(ha);
    float rb = b - __bfloat162float(hb);
    __nv_bfloat162 H; H.x = ha; H.y = hb;
    __nv_bfloat162 L = __floats2bfloat162_rn(ra, rb);
    hi = *(uint32_t*)&H;
    lo = *(uint32_t*)&L;
}

// ---------------------------------------------------------------------------
// BN precompute
// ---------------------------------------------------------------------------
__global__ void bn_pre_kernel(const float* __restrict__ g1, const float* __restrict__ be1,
                              const float* __restrict__ m1, const float* __restrict__ v1,
                              const float* __restrict__ go, const float* __restrict__ bo,
                              const float* __restrict__ mo, const float* __restrict__ vo,
                              float* __restrict__ s1, float* __restrict__ t1,
                              float* __restrict__ so, float* __restrict__ to)
{
    int t = blockIdx.x * blockDim.x + threadIdx.x;
    if (t < LNUM * 2 * DIM) {
        float sc = g1[t] * rsqrtf(v1[t] + 1e-5f);
        s1[t] = sc;
        t1[t] = be1[t] - m1[t] * sc;
    }
    if (t < (LNUM - 1) * DIM) {
        float sc = go[t] * rsqrtf(vo[t] + 1e-5f);
        so[t] = sc;
        to[t] = bo[t] - mo[t] * sc;
    }
}

// ---------------------------------------------------------------------------
// Weight transpose + bf16 hi/lo split.
// ---------------------------------------------------------------------------
__global__ void wsplit_kernel(const float* __restrict__ W1, const float* __restrict__ W2,
                              __nv_bfloat16* __restrict__ w1h, __nv_bfloat16* __restrict__ w1l,
                              __nv_bfloat16* __restrict__ w2h, __nv_bfloat16* __restrict__ w2l)
{
    int idx = blockIdx.x * blockDim.x + threadIdx.x;
    const int tot = LNUM * 2 * DIM * DIM;
    if (idx >= tot) return;
    int l = idx / (2 * DIM * DIM);
    int rem = idx % (2 * DIM * DIM);
    {
        int n = rem / DIM, k = rem % DIM;
        float w = W1[(size_t)l * DIM * 2 * DIM + (size_t)k * 2 * DIM + n];
        __nv_bfloat16 h = __float2bfloat16_rn(w);
        w1h[idx] = h;
        w1l[idx] = __float2bfloat16_rn(w - __bfloat162float(h));
    }
    {
        int n2 = rem / (2 * DIM), k2 = rem % (2 * DIM);
        float w = W2[(size_t)l * 2 * DIM * DIM + (size_t)k2 * DIM + n2];
        __nv_bfloat16 h = __float2bfloat16_rn(w);
        w2h[idx] = h;
        w2l[idx] = __float2bfloat16_rn(w - __bfloat162float(h));
    }
}

// ---------------------------------------------------------------------------
// CSR build: zero counts -> histogram -> inclusive scan -> copy cursor -> fill
// ---------------------------------------------------------------------------
__global__ void zero_cnt_kernel(int* __restrict__ cnt, int n)
{
    int i = blockIdx.x * blockDim.x + threadIdx.x;
    if (i < n) cnt[i] = 0;
}
__global__ void hist_kernel(const int* __restrict__ dst, int* __restrict__ cnt, int E)
{
    int e = blockIdx.x * blockDim.x + threadIdx.x;
    if (e < E) atomicAdd(&cnt[dst[e] + 1], 1);
}
__global__ void scan_kernel(int* __restrict__ cnt, int n1)
{
    __shared__ int wsum[32];
    __shared__ int carry;
    int tid = threadIdx.x, lane = tid & 31, wid = tid >> 5;
    if (tid == 0) carry = 0;
    __syncthreads();
    for (int base = 0; base < n1; base += 1024) {
        int i = base + tid;
        int v = (i < n1) ? cnt[i] : 0;
        int s = v;
#pragma unroll
        for (int o = 1; o < 32; o <<= 1) {
            int t = __shfl_up_sync(0xffffffffu, s, o);
            if (lane >= o) s += t;
        }
        if (lane == 31) wsum[wid] = s;
        __syncthreads();
        if (wid == 0) {
            int w = wsum[lane];
#pragma unroll
            for (int o = 1; o < 32; o <<= 1) {
                int t = __shfl_up_sync(0xffffffffu, w, o);
                if (lane >= o) w += t;
            }
            wsum[lane] = w;
        }
        __syncthreads();
        int inc = s + (wid ? wsum[wid - 1] : 0) + carry;
        if (i < n1) cnt[i] = inc;
        __syncthreads();
        if (tid == 1023) carry = inc;
        __syncthreads();
    }
}
__global__ void cursor_kernel(const int* __restrict__ rowptr, int* __restrict__ cur, int n)
{
    int i = blockIdx.x * blockDim.x + threadIdx.x;
    if (i < n) cur[i] = rowptr[i];
}
__global__ void fill_kernel(const int* __restrict__ src, const int* __restrict__ dst,
                            int* __restrict__ cur, int* __restrict__ adj, int E)
{
    int e = blockIdx.x * blockDim.x + threadIdx.x;
    if (e < E) {
        int pos = atomicAdd(&cur[dst[e]], 1);
        adj[pos] = src[e];
    }
}

// ---------------------------------------------------------------------------
// Gather + GIN combine + bf16 split: out = split((1+eps)*h[node] + sum_nbr h[nbr])
// one warp per node, lane covers 4 floats
// ---------------------------------------------------------------------------
__global__ __launch_bounds__(256)
void gather_kernel(const float* __restrict__ h, const int* __restrict__ rowptr,
                   const int* __restrict__ adj, const float* __restrict__ epsp,
                   __nv_bfloat16* __restrict__ chi, __nv_bfloat16* __restrict__ clo, int N)
{
    int node = blockIdx.x * 8 + (threadIdx.x >> 5);
    int lane = threadIdx.x & 31;
    if (node >= N) return;

    int beg = rowptr[node], end = rowptr[node + 1];
    float4 s0 = make_float4(0.f, 0.f, 0.f, 0.f);
    float4 s1 = make_float4(0.f, 0.f, 0.f, 0.f);

    for (int e = beg; e < end; e += 32) {
        int a = (e + lane < end) ? __ldg(adj + e + lane) : -1;
        int cnt = min(32, end - e);
        int j = 0;
        for (; j + 1 < cnt; j += 2) {
            int n0 = __shfl_sync(0xffffffffu, a, j);
            int n1 = __shfl_sync(0xffffffffu, a, j + 1);
            float4 v0 = __ldg((const float4*)(h + (size_t)n0 * DIM) + lane);
            float4 v1 = __ldg((const float4*)(h + (size_t)n1 * DIM) + lane);
            s0.x += v0.x; s0.y += v0.y; s0.z += v0.z; s0.w += v0.w;
            s1.x += v1.x; s1.y += v1.y; s1.z += v1.z; s1.w += v1.w;
        }
        if (j < cnt) {
            int n0 = __shfl_sync(0xffffffffu, a, j);
            float4 v0 = __ldg((const float4*)(h + (size_t)n0 * DIM) + lane);
            s0.x += v0.x; s0.y += v0.y; s0.z += v0.z; s0.w += v0.w;
        }
    }

    float epsv = 1.0f + epsp[0];
    float4 hv = __ldg((const float4*)(h + (size_t)node * DIM) + lane);
    float4 c;
    c.x = fmaf(epsv, hv.x, s0.x + s1.x);
    c.y = fmaf(epsv, hv.y, s0.y + s1.y);
    c.z = fmaf(epsv, hv.z, s0.z + s1.z);
    c.w = fmaf(epsv, hv.w, s0.w + s1.w);

    uint32_t h01, l01, h23, l23;
    split2(c.x, c.y, h01, l01);
    split2(c.z, c.w, h23, l23);
    uint2* ph = (uint2*)(chi + (size_t)node * DIM) + lane;
    uint2* pl = (uint2*)(clo + (size_t)node * DIM) + lane;
    *ph = make_uint2(h01, h23);
    *pl = make_uint2(l01, l23);
}

// ---------------------------------------------------------------------------
// 3xBF16 mma.sync GEMM, all-bf16 operands (pre-split hi/lo in gmem)
//   block 128x128, 8 warps (2M x 4N), warp tile 64x32, BK=32 double-buffered.
//   Output: either fp32 (Cf) or split bf16 (Chi/Clo).
// ---------------------------------------------------------------------------
#define BK 32
#define ASTRIDE 40                 // bf16 per smem row (80 B, conflict-free)
#define ABUF_B (128 * ASTRIDE * 2) // 10240 B per buffer
#define STAGE_B (4 * ABUF_B)       // Ahi,Alo,Whi,Wlo

__global__ __launch_bounds__(256)
void gemm_mma_kernel(const __nv_bfloat16* __restrict__ Ahi, const __nv_bfloat16* __restrict__ Alo,
                     const __nv_bfloat16* __restrict__ Whi, const __nv_bfloat16* __restrict__ Wlo,
                     const float* __restrict__ bias, const float* __restrict__ bns,
                     const float* __restrict__ bnt,
                     float* __restrict__ Cf, __nv_bfloat16* __restrict__ Chi,
                     __nv_bfloat16* __restrict__ Clo,
                     int M, int K, int Nc, int relu)
{
    extern __shared__ char smem[];
    const int tid = threadIdx.x;
    const int lane = tid & 31, wid = tid >> 5;
    const int warpM = wid >> 2, warpN = wid & 3;
    const int rowBase = blockIdx.y * 128;
    const int colBase = blockIdx.x * 128;
    const uint32_t sbase = smem_to_u32(smem);

    float acc[4][4][4];
#pragma unroll
    for (int a = 0; a < 4; a++)
#pragma unroll
        for (int b = 0; b < 4; b++)
#pragma unroll
            for (int c = 0; c < 4; c++) acc[a][b][c] = 0.f;

    const int frow = lane & 15, fk = (lane >> 4) * 8;
    uint32_t offA[4], offB[2];
#pragma unroll
    for (int mf = 0; mf < 4; mf++)
        offA[mf] = ((warpM * 64 + mf * 16 + frow) * ASTRIDE + fk) * 2;
#pragma unroll
    for (int nb = 0; nb < 2; nb++)
        offB[nb] = ((warpN * 32 + nb * 16 + frow) * ASTRIDE + fk) * 2;

    const int nch = K / BK;

    uint64_t pah[4], pal[4], pwh[4], pwl[4];

    // ---- prefetch chunk 0 ----
#pragma unroll
    for (int i = 0; i < 4; i++) {
        int f = tid + i * 256;
        int r = f >> 3, q = f & 7;          // r: tile row, q: uint64 within 32 bf16
        int g = rowBase + r;
        if (g < M) {
            pah[i] = __ldg((const uint64_t*)(Ahi + (size_t)g * K) + q);
            pal[i] = __ldg((const uint64_t*)(Alo + (size_t)g * K) + q);
        } else { pah[i] = 0; pal[i] = 0; }
        pwh[i] = __ldg((const uint64_t*)(Whi + (size_t)(colBase + r) * K) + q);
        pwl[i] = __ldg((const uint64_t*)(Wlo + (size_t)(colBase + r) * K) + q);
    }

    int s = 0;
    for (int c = 0; c < nch; c++) {
        // ---- store prefetched regs into stage s ----
        {
            char* Ahi_s = smem + s * STAGE_B;
            char* Alo_s = Ahi_s + ABUF_B;
            char* Whi_s = Ahi_s + 2 * ABUF_B;
            char* Wlo_s = Ahi_s + 3 * ABUF_B;
#pragma unroll
            for (int i = 0; i < 4; i++) {
                int f = tid + i * 256;
                int r = f >> 3, q = f & 7;
                int so = r * (ASTRIDE * 2) + q * 8;
                *(uint64_t*)(Ahi_s + so) = pah[i];
                *(uint64_t*)(Alo_s + so) = pal[i];
                *(uint64_t*)(Whi_s + so) = pwh[i];
                *(uint64_t*)(Wlo_s + so) = pwl[i];
            }
        }
        __syncthreads();

        // ---- prefetch next chunk ----
        if (c + 1 < nch) {
            int k0 = (c + 1) * BK;
#pragma unroll
            for (int i = 0; i < 4; i++) {
                int f = tid + i * 256;
                int r = f >> 3, q = f & 7;
                int g = rowBase + r;
                if (g < M) {
                    pah[i] = __ldg((const uint64_t*)(Ahi + (size_t)g * K + k0) + q);
                    pal[i] = __ldg((const uint64_t*)(Alo + (size_t)g * K + k0) + q);
                } else { pah[i] = 0; pal[i] = 0; }
                pwh[i] = __ldg((const uint64_t*)(Whi + (size_t)(colBase + r) * K + k0) + q);
                pwl[i] = __ldg((const uint64_t*)(Wlo + (size_t)(colBase + r) * K + k0) + q);
            }
        }

        // ---- mma over stage s: 2 k16 steps ----
        uint32_t bufA_hi = sbase + s * STAGE_B;
        uint32_t bufA_lo = bufA_hi + ABUF_B;
        uint32_t bufW_hi = bufA_hi + 2 * ABUF_B;
        uint32_t bufW_lo = bufA_hi + 3 * ABUF_B;
#pragma unroll
        for (int ks = 0; ks < 2; ks++) {
            uint32_t ah[4][4], al[4][4], bh[2][4], bl[2][4];
#pragma unroll
            for (int mf = 0; mf < 4; mf++) {
                ldmx4(ah[mf], bufA_hi + offA[mf] + ks * 32);
                ldmx4(al[mf], bufA_lo + offA[mf] + ks * 32);
            }
#pragma unroll
            for (int nb = 0; nb < 2; nb++) {
                ldmx4(bh[nb], bufW_hi + offB[nb] + ks * 32);
                ldmx4(bl[nb], bufW_lo + offB[nb] + ks * 32);
            }
#pragma unroll
            for (int mf = 0; mf < 4; mf++) {
#pragma unroll
                for (int nf = 0; nf < 4; nf++) {
                    int nb = nf >> 1, sel = nf & 1;
                    uint32_t b0h = bh[nb][sel], b1h = bh[nb][sel + 2];
                    uint32_t b0l = bl[nb][sel], b1l = bl[nb][sel + 2];
                    mma_bf16(acc[mf][nf], ah[mf], b0h, b1h);
                    mma_bf16(acc[mf][nf], ah[mf], b0l, b1l);
                    mma_bf16(acc[mf][nf], al[mf], b0h, b1h);
                }
            }
        }
        __syncthreads();
        s ^= 1;
    }

    // ---- epilogue ----
    const int g = lane >> 2, tig = lane & 3;
    float bj0[4], bj1[4], sj0[4], sj1[4], tj0[4], tj1[4];
#pragma unroll
    for (int nf = 0; nf < 4; nf++) {
        int col = colBase + warpN * 32 + nf * 8 + 2 * tig;
        bj0[nf] = bias[col];
        bj1[nf] = bias[col + 1];
        if (bns) {
            sj0[nf] = bns[col];  sj1[nf] = bns[col + 1];
            tj0[nf] = bnt[col];  tj1[nf] = bnt[col + 1];
        }
    }
#pragma unroll
    for (int mf = 0; mf < 4; mf++) {
#pragma unroll
        for (int half = 0; half < 2; half++) {
            int row = rowBase + warpM * 64 + mf * 16 + g + half * 8;
            if (row >= M) continue;
#pragma unroll
            for (int nf = 0; nf < 4; nf++) {
                int col = colBase + warpN * 32 + nf * 8 + 2 * tig;
                float v0 = acc[mf][nf][half * 2 + 0] + bj0[nf];
                float v1 = acc[mf][nf][half * 2 + 1] + bj1[nf];
                if (bns) {
                    v0 = fmaf(v0, sj0[nf], tj0[nf]);
                    v1 = fmaf(v1, sj1[nf], tj1[nf]);
                }
                if (relu) { v0 = fmaxf(v0, 0.f); v1 = fmaxf(v1, 0.f); }
                if (Cf) {
                    *(float2*)(Cf + (size_t)row * Nc + col) = make_float2(v0, v1);
                } else {
                    uint32_t hi, lo;
                    split2(v0, v1, hi, lo);
                    *(uint32_t*)(Chi + (size_t)row * Nc + col) = hi;
                    *(uint32_t*)(Clo + (size_t)row * Nc + col) = lo;
                }
            }
        }
    }
}

// ---------------------------------------------------------------------------
// log_softmax over 128 columns, one block per row
// ---------------------------------------------------------------------------
__global__ void logsoftmax_kernel(float* __restrict__ C)
{
    __shared__ float red[DIM];
    int row = blockIdx.x;
    int tid = threadIdx.x;
    float v = C[(size_t)row * DIM + tid];

    red[tid] = v;
    __syncthreads();
    for (int s = DIM / 2; s > 0; s >>= 1) {
        if (tid < s) red[tid] = fmaxf(red[tid], red[tid + s]);
        __syncthreads();
    }
    float m = red[0];
    __syncthreads();

    float e = expf(v - m);
    red[tid] = e;
    __syncthreads();
    for (int s = DIM / 2; s > 0; s >>= 1) {
        if (tid < s) red[tid] += red[tid + s];
        __syncthreads();
    }
    float sum = red[0];

    C[(size_t)row * DIM + tid] = v - m - logf(sum);
}

// ---------------------------------------------------------------------------
extern "C" void kernel_launch(void* const* d_in, const int* in_sizes, int n_in,
                              void* d_out, int out_size)
{
    const float* x    = (const float*)d_in[0];
    const int*   ei   = (const int*)  d_in[1];
    const float* W1   = (const float*)d_in[2];
    const float* b1   = (const float*)d_in[3];
    const float* g1   = (const float*)d_in[4];
    const float* be1  = (const float*)d_in[5];
    const float* m1   = (const float*)d_in[6];
    const float* v1   = (const float*)d_in[7];
    const float* W2   = (const float*)d_in[8];
    const float* b2   = (const float*)d_in[9];
    const float* eps  = (const float*)d_in[10];
    const float* go   = (const float*)d_in[11];
    const float* bo   = (const float*)d_in[12];
    const float* mo   = (const float*)d_in[13];
    const float* vo   = (const float*)d_in[14];

    int N = in_sizes[0] / DIM;
    int E = in_sizes[1] / 2;

    float *hbuf, *s1, *t1, *so, *to;
    __nv_bfloat16 *chi, *clo, *zhi, *zlo, *w1h, *w1l, *w2h, *w2l;
    int *rowptr, *cursor, *adj;
    cudaGetSymbolAddress((void**)&hbuf,   g_h);
    cudaGetSymbolAddress((void**)&chi,    g_chi);
    cudaGetSymbolAddress((void**)&clo,    g_clo);
    cudaGetSymbolAddress((void**)&zhi,    g_zhi);
    cudaGetSymbolAddress((void**)&zlo,    g_zlo);
    cudaGetSymbolAddress((void**)&s1,     g_s1);
    cudaGetSymbolAddress((void**)&t1,     g_t1);
    cudaGetSymbolAddress((void**)&so,     g_so);
    cudaGetSymbolAddress((void**)&to,     g_to);
    cudaGetSymbolAddress((void**)&w1h,    g_w1hi);
    cudaGetSymbolAddress((void**)&w1l,    g_w1lo);
    cudaGetSymbolAddress((void**)&w2h,    g_w2hi);
    cudaGetSymbolAddress((void**)&w2l,    g_w2lo);
    cudaGetSymbolAddress((void**)&rowptr, g_rowptr);
    cudaGetSymbolAddress((void**)&cursor, g_cursor);
    cudaGetSymbolAddress((void**)&adj,    g_adj);

    const int dynSmem = 2 * STAGE_B;  // 81920 B
    cudaFuncSetAttribute(gemm_mma_kernel, cudaFuncAttributeMaxDynamicSharedMemorySize, dynSmem);

    const int* src = ei;
    const int* dst = ei + E;

    // ---- setup: BN folding, weight split, CSR build ----
    bn_pre_kernel<<<1, LNUM * 2 * DIM>>>(g1, be1, m1, v1, go, bo, mo, vo, s1, t1, so, to);
    {
        int tot = LNUM * 2 * DIM * DIM;
        wsplit_kernel<<<(tot + 255) / 256, 256>>>(W1, W2, w1h, w1l, w2h, w2l);
    }
    zero_cnt_kernel<<<(N + 1 + 255) / 256, 256>>>(rowptr, N + 1);
    hist_kernel<<<(E + 255) / 256, 256>>>(dst, rowptr, E);
    scan_kernel<<<1, 1024>>>(rowptr, N + 1);
    cursor_kernel<<<(N + 255) / 256, 256>>>(rowptr, cursor, N);
    fill_kernel<<<(E + 255) / 256, 256>>>(src, dst, cursor, adj, E);

    int mblocks = (N + 127) / 128;
    int gblocks = (N + 7) / 8;

    const float* h = x;
    for (int i = 0; i < LNUM; i++) {
        // gather + combine + split -> chi/clo [N,128]
        gather_kernel<<<gblocks, 256>>>(h, rowptr, adj, eps + i, chi, clo, N);

        // GEMM1: z[N,256] = combine @ W1 -> bias, BN, ReLU -> split zhi/zlo
        dim3 grid1(2, mblocks);
        gemm_mma_kernel<<<grid1, 256, dynSmem>>>(chi, clo,
                                                 w1h + (size_t)i * 2 * DIM * DIM,
                                                 w1l + (size_t)i * 2 * DIM * DIM,
                                                 b1 + (size_t)i * 2 * DIM,
                                                 s1 + (size_t)i * 2 * DIM,
                                                 t1 + (size_t)i * 2 * DIM,
                                                 nullptr, zhi, zlo,
                                                 N, DIM, 2 * DIM, 1);

        dim3 grid2(1, mblocks);
        if (i < LNUM - 1) {
            // GEMM2: h[N,128] fp32 = z @ W2 -> bias, BN, ReLU
            gemm_mma_kernel<<<grid2, 256, dynSmem>>>(zhi, zlo,
                                                     w2h + (size_t)i * 2 * DIM * DIM,
                                                     w2l + (size_t)i * 2 * DIM * DIM,
                                                     b2 + (size_t)i * DIM,
                                                     so + (size_t)i * DIM,
                                                     to + (size_t)i * DIM,
                                                     hbuf, nullptr, nullptr,
                                                     N, 2 * DIM, DIM, 1);
            h = hbuf;
        } else {
            gemm_mma_kernel<<<grid2, 256, dynSmem>>>(zhi, zlo,
                                                     w2h + (size_t)i * 2 * DIM * DIM,
                                                     w2l + (size_t)i * 2 * DIM * DIM,
                                                     b2 + (size_t)i * DIM,
                                                     nullptr, nullptr,
                                                     (float*)d_out, nullptr, nullptr,
                                                     N, 2 * DIM, DIM, 0);
        }
    }

    logsoftmax_kernel<<<N, DIM>>>((float*)d_out);
}

// round 6
// speedup vs baseline: 3.7632x; 1.3641x over previous
#include <cuda_runtime.h>
#include <cuda_fp16.h>
#include <cstdint>
#include <math.h>

#define NMAX 50000
#define EMAX 800000
#define DIM  128
#define LNUM 3

// ---------------------------------------------------------------------------
// scratch (no allocation allowed)
// ---------------------------------------------------------------------------
__device__ float g_h  [(size_t)NMAX * DIM];         // fp32 activations between layers
__device__ __half g_chi[(size_t)NMAX * DIM];        // combine hi (GEMM1 input)
__device__ __half g_clo[(size_t)NMAX * DIM];        // combine lo
__device__ __half g_zhi[(size_t)NMAX * 2 * DIM];    // z hi (GEMM2 input)
__device__ __half g_zlo[(size_t)NMAX * 2 * DIM];    // z lo
__device__ float g_s1[LNUM * 2 * DIM];
__device__ float g_t1[LNUM * 2 * DIM];
__device__ float g_so[(LNUM - 1) * DIM];
__device__ float g_to[(LNUM - 1) * DIM];
// transposed fp16 weights: W1T [L][256][128], W2T [L][128][256]
__device__ __half g_w1[LNUM * 2 * DIM * DIM];
__device__ __half g_w2[LNUM * 2 * DIM * DIM];
// CSR
__device__ int g_rowptr[NMAX + 1];
__device__ int g_cursor[NMAX];
__device__ int g_adj[EMAX];

// ---------------------------------------------------------------------------
// helpers
// ---------------------------------------------------------------------------
__device__ __forceinline__ uint32_t smem_to_u32(const void* p) {
    uint32_t a;
    asm("{ .reg .u64 t; cvta.to.shared.u64 t, %1; cvt.u32.u64 %0, t; }" : "=r"(a) : "l"(p));
    return a;
}
__device__ __forceinline__ void ldmx4(uint32_t* r, uint32_t addr) {
    asm volatile("ldmatrix.sync.aligned.m8n8.x4.shared.b16 {%0,%1,%2,%3}, [%4];"
                 : "=r"(r[0]), "=r"(r[1]), "=r"(r[2]), "=r"(r[3]) : "r"(addr));
}
__device__ __forceinline__ void mma_f16(float* c, const uint32_t* a, uint32_t b0, uint32_t b1) {
    asm volatile("mma.sync.aligned.m16n8k16.row.col.f32.f16.f16.f32 "
                 "{%0,%1,%2,%3}, {%4,%5,%6,%7}, {%8,%9}, {%0,%1,%2,%3};"
                 : "+f"(c[0]), "+f"(c[1]), "+f"(c[2]), "+f"(c[3])
                 : "r"(a[0]), "r"(a[1]), "r"(a[2]), "r"(a[3]), "r"(b0), "r"(b1));
}
// split two floats into packed fp16 hi pair + fp16 lo (residual) pair
__device__ __forceinline__ void split2h(float a, float b, uint32_t& hi, uint32_t& lo) {
    __half2 H = __floats2half2_rn(a, b);
    float ra = a - __half2float(__low2half(H));
    float rb = b - __half2float(__high2half(H));
    __half2 L = __floats2half2_rn(ra, rb);
    hi = *(uint32_t*)&H;
    lo = *(uint32_t*)&L;
}

// ---------------------------------------------------------------------------
// BN precompute
// ---------------------------------------------------------------------------
__global__ void bn_pre_kernel(const float* __restrict__ g1, const float* __restrict__ be1,
                              const float* __restrict__ m1, const float* __restrict__ v1,
                              const float* __restrict__ go, const float* __restrict__ bo,
                              const float* __restrict__ mo, const float* __restrict__ vo,
                              float* __restrict__ s1, float* __restrict__ t1,
                              float* __restrict__ so, float* __restrict__ to)
{
    int t = blockIdx.x * blockDim.x + threadIdx.x;
    if (t < LNUM * 2 * DIM) {
        float sc = g1[t] * rsqrtf(v1[t] + 1e-5f);
        s1[t] = sc;
        t1[t] = be1[t] - m1[t] * sc;
    }
    if (t < (LNUM - 1) * DIM) {
        float sc = go[t] * rsqrtf(vo[t] + 1e-5f);
        so[t] = sc;
        to[t] = bo[t] - mo[t] * sc;
    }
}

// ---------------------------------------------------------------------------
// Weight transpose + fp16 round.
// W1 [l][k=128][n=256] -> W1T [l][n][k];  W2 [l][k=256][n=128] -> W2T [l][n][k]
// ---------------------------------------------------------------------------
__global__ void wconv_kernel(const float* __restrict__ W1, const float* __restrict__ W2,
                             __half* __restrict__ w1, __half* __restrict__ w2)
{
    int idx = blockIdx.x * blockDim.x + threadIdx.x;
    const int tot = LNUM * 2 * DIM * DIM;
    if (idx >= tot) return;
    int l = idx / (2 * DIM * DIM);
    int rem = idx % (2 * DIM * DIM);
    {
        int n = rem / DIM, k = rem % DIM;
        w1[idx] = __float2half_rn(W1[(size_t)l * DIM * 2 * DIM + (size_t)k * 2 * DIM + n]);
    }
    {
        int n2 = rem / (2 * DIM), k2 = rem % (2 * DIM);
        w2[idx] = __float2half_rn(W2[(size_t)l * 2 * DIM * DIM + (size_t)k2 * DIM + n2]);
    }
}

// ---------------------------------------------------------------------------
// CSR build: zero counts -> histogram -> inclusive scan -> copy cursor -> fill
// ---------------------------------------------------------------------------
__global__ void zero_cnt_kernel(int* __restrict__ cnt, int n)
{
    int i = blockIdx.x * blockDim.x + threadIdx.x;
    if (i < n) cnt[i] = 0;
}
__global__ void hist_kernel(const int* __restrict__ dst, int* __restrict__ cnt, int E)
{
    int e = blockIdx.x * blockDim.x + threadIdx.x;
    if (e < E) atomicAdd(&cnt[dst[e] + 1], 1);
}
__global__ void scan_kernel(int* __restrict__ cnt, int n1)
{
    __shared__ int wsum[32];
    __shared__ int carry;
    int tid = threadIdx.x, lane = tid & 31, wid = tid >> 5;
    if (tid == 0) carry = 0;
    __syncthreads();
    for (int base = 0; base < n1; base += 1024) {
        int i = base + tid;
        int v = (i < n1) ? cnt[i] : 0;
        int s = v;
#pragma unroll
        for (int o = 1; o < 32; o <<= 1) {
            int t = __shfl_up_sync(0xffffffffu, s, o);
            if (lane >= o) s += t;
        }
        if (lane == 31) wsum[wid] = s;
        __syncthreads();
        if (wid == 0) {
            int w = wsum[lane];
#pragma unroll
            for (int o = 1; o < 32; o <<= 1) {
                int t = __shfl_up_sync(0xffffffffu, w, o);
                if (lane >= o) w += t;
            }
            wsum[lane] = w;
        }
        __syncthreads();
        int inc = s + (wid ? wsum[wid - 1] : 0) + carry;
        if (i < n1) cnt[i] = inc;
        __syncthreads();
        if (tid == 1023) carry = inc;
        __syncthreads();
    }
}
__global__ void cursor_kernel(const int* __restrict__ rowptr, int* __restrict__ cur, int n)
{
    int i = blockIdx.x * blockDim.x + threadIdx.x;
    if (i < n) cur[i] = rowptr[i];
}
__global__ void fill_kernel(const int* __restrict__ src, const int* __restrict__ dst,
                            int* __restrict__ cur, int* __restrict__ adj, int E)
{
    int e = blockIdx.x * blockDim.x + threadIdx.x;
    if (e < E) {
        int pos = atomicAdd(&cur[dst[e]], 1);
        adj[pos] = src[e];
    }
}

// ---------------------------------------------------------------------------
// Gather + GIN combine + fp16 split: out = split((1+eps)*h[node] + sum_nbr h[nbr])
// one warp per node, lane covers 4 floats
// ---------------------------------------------------------------------------
__global__ __launch_bounds__(256)
void gather_kernel(const float* __restrict__ h, const int* __restrict__ rowptr,
                   const int* __restrict__ adj, const float* __restrict__ epsp,
                   __half* __restrict__ chi, __half* __restrict__ clo, int N)
{
    int node = blockIdx.x * 8 + (threadIdx.x >> 5);
    int lane = threadIdx.x & 31;
    if (node >= N) return;

    int beg = rowptr[node], end = rowptr[node + 1];
    float4 s0 = make_float4(0.f, 0.f, 0.f, 0.f);
    float4 s1 = make_float4(0.f, 0.f, 0.f, 0.f);

    for (int e = beg; e < end; e += 32) {
        int a = (e + lane < end) ? __ldg(adj + e + lane) : -1;
        int cnt = min(32, end - e);
        int j = 0;
        for (; j + 1 < cnt; j += 2) {
            int n0 = __shfl_sync(0xffffffffu, a, j);
            int n1 = __shfl_sync(0xffffffffu, a, j + 1);
            float4 v0 = __ldg((const float4*)(h + (size_t)n0 * DIM) + lane);
            float4 v1 = __ldg((const float4*)(h + (size_t)n1 * DIM) + lane);
            s0.x += v0.x; s0.y += v0.y; s0.z += v0.z; s0.w += v0.w;
            s1.x += v1.x; s1.y += v1.y; s1.z += v1.z; s1.w += v1.w;
        }
        if (j < cnt) {
            int n0 = __shfl_sync(0xffffffffu, a, j);
            float4 v0 = __ldg((const float4*)(h + (size_t)n0 * DIM) + lane);
            s0.x += v0.x; s0.y += v0.y; s0.z += v0.z; s0.w += v0.w;
        }
    }

    float epsv = 1.0f + epsp[0];
    float4 hv = __ldg((const float4*)(h + (size_t)node * DIM) + lane);
    float4 c;
    c.x = fmaf(epsv, hv.x, s0.x + s1.x);
    c.y = fmaf(epsv, hv.y, s0.y + s1.y);
    c.z = fmaf(epsv, hv.z, s0.z + s1.z);
    c.w = fmaf(epsv, hv.w, s0.w + s1.w);

    uint32_t h01, l01, h23, l23;
    split2h(c.x, c.y, h01, l01);
    split2h(c.z, c.w, h23, l23);
    uint2* ph = (uint2*)(chi + (size_t)node * DIM) + lane;
    uint2* pl = (uint2*)(clo + (size_t)node * DIM) + lane;
    *ph = make_uint2(h01, h23);
    *pl = make_uint2(l01, l23);
}

// ---------------------------------------------------------------------------
// 2xFP16 mma.sync GEMM: C = act(bn((Ahi+Alo) @ W + bias)),  W fp16 single.
//   block 128x128, 8 warps (2M x 4N), warp tile 64x32, BK=32 double-buffered.
//   Output: fp32 (Cf) or split fp16 (Chi/Clo).
// ---------------------------------------------------------------------------
#define BK 32
#define ASTRIDE 40                 // fp16 per smem row (80 B, conflict-free)
#define ABUF_B (128 * ASTRIDE * 2) // 10240 B per buffer
#define STAGE_B (3 * ABUF_B)       // Ahi, Alo, W

__global__ __launch_bounds__(256)
void gemm_mma_kernel(const __half* __restrict__ Ahi, const __half* __restrict__ Alo,
                     const __half* __restrict__ W,
                     const float* __restrict__ bias, const float* __restrict__ bns,
                     const float* __restrict__ bnt,
                     float* __restrict__ Cf, __half* __restrict__ Chi,
                     __half* __restrict__ Clo,
                     int M, int K, int Nc, int relu)
{
    extern __shared__ char smem[];
    const int tid = threadIdx.x;
    const int lane = tid & 31, wid = tid >> 5;
    const int warpM = wid >> 2, warpN = wid & 3;
    const int rowBase = blockIdx.y * 128;
    const int colBase = blockIdx.x * 128;
    const uint32_t sbase = smem_to_u32(smem);

    float acc[4][4][4];
#pragma unroll
    for (int a = 0; a < 4; a++)
#pragma unroll
        for (int b = 0; b < 4; b++)
#pragma unroll
            for (int c = 0; c < 4; c++) acc[a][b][c] = 0.f;

    const int frow = lane & 15, fk = (lane >> 4) * 8;
    uint32_t offA[4], offB[2];
#pragma unroll
    for (int mf = 0; mf < 4; mf++)
        offA[mf] = ((warpM * 64 + mf * 16 + frow) * ASTRIDE + fk) * 2;
#pragma unroll
    for (int nb = 0; nb < 2; nb++)
        offB[nb] = ((warpN * 32 + nb * 16 + frow) * ASTRIDE + fk) * 2;

    const int nch = K / BK;

    uint64_t pah[4], pal[4], pw[4];

    // ---- prefetch chunk 0 ----
#pragma unroll
    for (int i = 0; i < 4; i++) {
        int f = tid + i * 256;
        int r = f >> 3, q = f & 7;
        int g = rowBase + r;
        if (g < M) {
            pah[i] = __ldg((const uint64_t*)(Ahi + (size_t)g * K) + q);
            pal[i] = __ldg((const uint64_t*)(Alo + (size_t)g * K) + q);
        } else { pah[i] = 0; pal[i] = 0; }
        pw[i] = __ldg((const uint64_t*)(W + (size_t)(colBase + r) * K) + q);
    }

    int s = 0;
    for (int c = 0; c < nch; c++) {
        // ---- store prefetched regs into stage s ----
        {
            char* Ahi_s = smem + s * STAGE_B;
            char* Alo_s = Ahi_s + ABUF_B;
            char* W_s   = Ahi_s + 2 * ABUF_B;
#pragma unroll
            for (int i = 0; i < 4; i++) {
                int f = tid + i * 256;
                int r = f >> 3, q = f & 7;
                int so = r * (ASTRIDE * 2) + q * 8;
                *(uint64_t*)(Ahi_s + so) = pah[i];
                *(uint64_t*)(Alo_s + so) = pal[i];
                *(uint64_t*)(W_s   + so) = pw[i];
            }
        }
        __syncthreads();

        // ---- prefetch next chunk ----
        if (c + 1 < nch) {
            int k0 = (c + 1) * BK;
#pragma unroll
            for (int i = 0; i < 4; i++) {
                int f = tid + i * 256;
                int r = f >> 3, q = f & 7;
                int g = rowBase + r;
                if (g < M) {
                    pah[i] = __ldg((const uint64_t*)(Ahi + (size_t)g * K + k0) + q);
                    pal[i] = __ldg((const uint64_t*)(Alo + (size_t)g * K + k0) + q);
                } else { pah[i] = 0; pal[i] = 0; }
                pw[i] = __ldg((const uint64_t*)(W + (size_t)(colBase + r) * K + k0) + q);
            }
        }

        // ---- mma over stage s: 2 k16 steps ----
        uint32_t bufA_hi = sbase + s * STAGE_B;
        uint32_t bufA_lo = bufA_hi + ABUF_B;
        uint32_t bufW    = bufA_hi + 2 * ABUF_B;
#pragma unroll
        for (int ks = 0; ks < 2; ks++) {
            uint32_t ah[4][4], al[4][4], bw[2][4];
#pragma unroll
            for (int mf = 0; mf < 4; mf++) {
                ldmx4(ah[mf], bufA_hi + offA[mf] + ks * 32);
                ldmx4(al[mf], bufA_lo + offA[mf] + ks * 32);
            }
#pragma unroll
            for (int nb = 0; nb < 2; nb++)
                ldmx4(bw[nb], bufW + offB[nb] + ks * 32);
#pragma unroll
            for (int mf = 0; mf < 4; mf++) {
#pragma unroll
                for (int nf = 0; nf < 4; nf++) {
                    int nb = nf >> 1, sel = nf & 1;
                    uint32_t b0 = bw[nb][sel], b1 = bw[nb][sel + 2];
                    mma_f16(acc[mf][nf], ah[mf], b0, b1);
                    mma_f16(acc[mf][nf], al[mf], b0, b1);
                }
            }
        }
        __syncthreads();
        s ^= 1;
    }

    // ---- epilogue ----
    const int g = lane >> 2, tig = lane & 3;
    float bj0[4], bj1[4], sj0[4], sj1[4], tj0[4], tj1[4];
#pragma unroll
    for (int nf = 0; nf < 4; nf++) {
        int col = colBase + warpN * 32 + nf * 8 + 2 * tig;
        bj0[nf] = bias[col];
        bj1[nf] = bias[col + 1];
        if (bns) {
            sj0[nf] = bns[col];  sj1[nf] = bns[col + 1];
            tj0[nf] = bnt[col];  tj1[nf] = bnt[col + 1];
        }
    }
#pragma unroll
    for (int mf = 0; mf < 4; mf++) {
#pragma unroll
        for (int half = 0; half < 2; half++) {
            int row = rowBase + warpM * 64 + mf * 16 + g + half * 8;
            if (row >= M) continue;
#pragma unroll
            for (int nf = 0; nf < 4; nf++) {
                int col = colBase + warpN * 32 + nf * 8 + 2 * tig;
                float v0 = acc[mf][nf][half * 2 + 0] + bj0[nf];
                float v1 = acc[mf][nf][half * 2 + 1] + bj1[nf];
                if (bns) {
                    v0 = fmaf(v0, sj0[nf], tj0[nf]);
                    v1 = fmaf(v1, sj1[nf], tj1[nf]);
                }
                if (relu) { v0 = fmaxf(v0, 0.f); v1 = fmaxf(v1, 0.f); }
                if (Cf) {
                    *(float2*)(Cf + (size_t)row * Nc + col) = make_float2(v0, v1);
                } else {
                    uint32_t hi, lo;
                    split2h(v0, v1, hi, lo);
                    *(uint32_t*)(Chi + (size_t)row * Nc + col) = hi;
                    *(uint32_t*)(Clo + (size_t)row * Nc + col) = lo;
                }
            }
        }
    }
}

// ---------------------------------------------------------------------------
// log_softmax: one warp per row, lane covers 4 cols
// ---------------------------------------------------------------------------
__global__ __launch_bounds__(128)
void logsoftmax_kernel(float* __restrict__ C, int N)
{
    int row = blockIdx.x * 4 + (threadIdx.x >> 5);
    int lane = threadIdx.x & 31;
    if (row >= N) return;
    float4 v = *((const float4*)(C + (size_t)row * DIM) + lane);
    float m = fmaxf(fmaxf(v.x, v.y), fmaxf(v.z, v.w));
#pragma unroll
    for (int o = 16; o > 0; o >>= 1)
        m = fmaxf(m, __shfl_xor_sync(0xffffffffu, m, o));
    float e = expf(v.x - m) + expf(v.y - m) + expf(v.z - m) + expf(v.w - m);
#pragma unroll
    for (int o = 16; o > 0; o >>= 1)
        e += __shfl_xor_sync(0xffffffffu, e, o);
    float lse = m + logf(e);
    v.x -= lse; v.y -= lse; v.z -= lse; v.w -= lse;
    *((float4*)(C + (size_t)row * DIM) + lane) = v;
}

// ---------------------------------------------------------------------------
extern "C" void kernel_launch(void* const* d_in, const int* in_sizes, int n_in,
                              void* d_out, int out_size)
{
    const float* x    = (const float*)d_in[0];
    const int*   ei   = (const int*)  d_in[1];
    const float* W1   = (const float*)d_in[2];
    const float* b1   = (const float*)d_in[3];
    const float* g1   = (const float*)d_in[4];
    const float* be1  = (const float*)d_in[5];
    const float* m1   = (const float*)d_in[6];
    const float* v1   = (const float*)d_in[7];
    const float* W2   = (const float*)d_in[8];
    const float* b2   = (const float*)d_in[9];
    const float* eps  = (const float*)d_in[10];
    const float* go   = (const float*)d_in[11];
    const float* bo   = (const float*)d_in[12];
    const float* mo   = (const float*)d_in[13];
    const float* vo   = (const float*)d_in[14];

    int N = in_sizes[0] / DIM;
    int E = in_sizes[1] / 2;

    float *hbuf, *s1, *t1, *so, *to;
    __half *chi, *clo, *zhi, *zlo, *w1, *w2;
    int *rowptr, *cursor, *adj;
    cudaGetSymbolAddress((void**)&hbuf,   g_h);
    cudaGetSymbolAddress((void**)&chi,    g_chi);
    cudaGetSymbolAddress((void**)&clo,    g_clo);
    cudaGetSymbolAddress((void**)&zhi,    g_zhi);
    cudaGetSymbolAddress((void**)&zlo,    g_zlo);
    cudaGetSymbolAddress((void**)&s1,     g_s1);
    cudaGetSymbolAddress((void**)&t1,     g_t1);
    cudaGetSymbolAddress((void**)&so,     g_so);
    cudaGetSymbolAddress((void**)&to,     g_to);
    cudaGetSymbolAddress((void**)&w1,     g_w1);
    cudaGetSymbolAddress((void**)&w2,     g_w2);
    cudaGetSymbolAddress((void**)&rowptr, g_rowptr);
    cudaGetSymbolAddress((void**)&cursor, g_cursor);
    cudaGetSymbolAddress((void**)&adj,    g_adj);

    const int dynSmem = 2 * STAGE_B;  // 61440 B
    cudaFuncSetAttribute(gemm_mma_kernel, cudaFuncAttributeMaxDynamicSharedMemorySize, dynSmem);

    const int* src = ei;
    const int* dst = ei + E;

    // ---- setup: BN folding, weight conversion, CSR build ----
    bn_pre_kernel<<<1, LNUM * 2 * DIM>>>(g1, be1, m1, v1, go, bo, mo, vo, s1, t1, so, to);
    {
        int tot = LNUM * 2 * DIM * DIM;
        wconv_kernel<<<(tot + 255) / 256, 256>>>(W1, W2, w1, w2);
    }
    zero_cnt_kernel<<<(N + 1 + 255) / 256, 256>>>(rowptr, N + 1);
    hist_kernel<<<(E + 255) / 256, 256>>>(dst, rowptr, E);
    scan_kernel<<<1, 1024>>>(rowptr, N + 1);
    cursor_kernel<<<(N + 255) / 256, 256>>>(rowptr, cursor, N);
    fill_kernel<<<(E + 255) / 256, 256>>>(src, dst, cursor, adj, E);

    int mblocks = (N + 127) / 128;
    int gblocks = (N + 7) / 8;

    const float* h = x;
    for (int i = 0; i < LNUM; i++) {
        // gather + combine + split -> chi/clo [N,128]
        gather_kernel<<<gblocks, 256>>>(h, rowptr, adj, eps + i, chi, clo, N);

        // GEMM1: z[N,256] = combine @ W1 -> bias, BN, ReLU -> split zhi/zlo
        dim3 grid1(2, mblocks);
        gemm_mma_kernel<<<grid1, 256, dynSmem>>>(chi, clo,
                                                 w1 + (size_t)i * 2 * DIM * DIM,
                                                 b1 + (size_t)i * 2 * DIM,
                                                 s1 + (size_t)i * 2 * DIM,
                                                 t1 + (size_t)i * 2 * DIM,
                                                 nullptr, zhi, zlo,
                                                 N, DIM, 2 * DIM, 1);

        dim3 grid2(1, mblocks);
        if (i < LNUM - 1) {
            // GEMM2: h[N,128] fp32 = z @ W2 -> bias, BN, ReLU
            gemm_mma_kernel<<<grid2, 256, dynSmem>>>(zhi, zlo,
                                                     w2 + (size_t)i * 2 * DIM * DIM,
                                                     b2 + (size_t)i * DIM,
                                                     so + (size_t)i * DIM,
                                                     to + (size_t)i * DIM,
                                                     hbuf, nullptr, nullptr,
                                                     N, 2 * DIM, DIM, 1);
            h = hbuf;
        } else {
            gemm_mma_kernel<<<grid2, 256, dynSmem>>>(zhi, zlo,
                                                     w2 + (size_t)i * 2 * DIM * DIM,
                                                     b2 + (size_t)i * DIM,
                                                     nullptr, nullptr,
                                                     (float*)d_out, nullptr, nullptr,
                                                     N, 2 * DIM, DIM, 0);
        }
    }

    logsoftmax_kernel<<<(N + 3) / 4, 128>>>((float*)d_out, N);
}

// round 7
// speedup vs baseline: 3.7844x; 1.0056x over previous
#include <cuda_runtime.h>
#include <cuda_fp16.h>
#include <cstdint>
#include <math.h>

#define NMAX 50000
#define EMAX 800000
#define DIM  128
#define LNUM 3

// ---------------------------------------------------------------------------
// scratch (no allocation allowed)
// ---------------------------------------------------------------------------
__device__ __half g_hh [(size_t)NMAX * DIM];        // fp16 activations between layers (and x)
__device__ __half g_chi[(size_t)NMAX * DIM];        // combine hi (GEMM1 input)
__device__ __half g_clo[(size_t)NMAX * DIM];        // combine lo
__device__ __half g_zhi[(size_t)NMAX * 2 * DIM];    // z hi (GEMM2 input)
__device__ __half g_zlo[(size_t)NMAX * 2 * DIM];    // z lo
__device__ float g_s1[LNUM * 2 * DIM];
__device__ float g_t1[LNUM * 2 * DIM];
__device__ float g_so[(LNUM - 1) * DIM];
__device__ float g_to[(LNUM - 1) * DIM];
// transposed fp16 weights: W1T [L][256][128], W2T [L][128][256]
__device__ __half g_w1[LNUM * 2 * DIM * DIM];
__device__ __half g_w2[LNUM * 2 * DIM * DIM];
// CSR
__device__ int g_rowptr[NMAX + 1];
__device__ int g_cursor[NMAX];
__device__ int g_adj[EMAX];

// ---------------------------------------------------------------------------
// helpers
// ---------------------------------------------------------------------------
__device__ __forceinline__ uint32_t smem_to_u32(const void* p) {
    uint32_t a;
    asm("{ .reg .u64 t; cvta.to.shared.u64 t, %1; cvt.u32.u64 %0, t; }" : "=r"(a) : "l"(p));
    return a;
}
__device__ __forceinline__ void ldmx4(uint32_t* r, uint32_t addr) {
    asm volatile("ldmatrix.sync.aligned.m8n8.x4.shared.b16 {%0,%1,%2,%3}, [%4];"
                 : "=r"(r[0]), "=r"(r[1]), "=r"(r[2]), "=r"(r[3]) : "r"(addr));
}
__device__ __forceinline__ void mma_f16(float* c, const uint32_t* a, uint32_t b0, uint32_t b1) {
    asm volatile("mma.sync.aligned.m16n8k16.row.col.f32.f16.f16.f32 "
                 "{%0,%1,%2,%3}, {%4,%5,%6,%7}, {%8,%9}, {%0,%1,%2,%3};"
                 : "+f"(c[0]), "+f"(c[1]), "+f"(c[2]), "+f"(c[3])
                 : "r"(a[0]), "r"(a[1]), "r"(a[2]), "r"(a[3]), "r"(b0), "r"(b1));
}
// split two floats into packed fp16 hi pair + fp16 lo (residual) pair
__device__ __forceinline__ void split2h(float a, float b, uint32_t& hi, uint32_t& lo) {
    __half2 H = __floats2half2_rn(a, b);
    float ra = a - __half2float(__low2half(H));
    float rb = b - __half2float(__high2half(H));
    __half2 L = __floats2half2_rn(ra, rb);
    hi = *(uint32_t*)&H;
    lo = *(uint32_t*)&L;
}

// ---------------------------------------------------------------------------
// BN precompute
// ---------------------------------------------------------------------------
__global__ void bn_pre_kernel(const float* __restrict__ g1, const float* __restrict__ be1,
                              const float* __restrict__ m1, const float* __restrict__ v1,
                              const float* __restrict__ go, const float* __restrict__ bo,
                              const float* __restrict__ mo, const float* __restrict__ vo,
                              float* __restrict__ s1, float* __restrict__ t1,
                              float* __restrict__ so, float* __restrict__ to)
{
    int t = blockIdx.x * blockDim.x + threadIdx.x;
    if (t < LNUM * 2 * DIM) {
        float sc = g1[t] * rsqrtf(v1[t] + 1e-5f);
        s1[t] = sc;
        t1[t] = be1[t] - m1[t] * sc;
    }
    if (t < (LNUM - 1) * DIM) {
        float sc = go[t] * rsqrtf(vo[t] + 1e-5f);
        so[t] = sc;
        to[t] = bo[t] - mo[t] * sc;
    }
}

// ---------------------------------------------------------------------------
// x -> fp16 pre-convert
// ---------------------------------------------------------------------------
__global__ void xconv_kernel(const float* __restrict__ x, __half* __restrict__ xh, int n)
{
    int i = blockIdx.x * blockDim.x + threadIdx.x;
    if (i < n) {
        float2 v = *((const float2*)x + i);
        __half2 p = __floats2half2_rn(v.x, v.y);
        *((__half2*)xh + i) = p;
    }
}

// ---------------------------------------------------------------------------
// Weight transpose + fp16 round.
// ---------------------------------------------------------------------------
__global__ void wconv_kernel(const float* __restrict__ W1, const float* __restrict__ W2,
                             __half* __restrict__ w1, __half* __restrict__ w2)
{
    int idx = blockIdx.x * blockDim.x + threadIdx.x;
    const int tot = LNUM * 2 * DIM * DIM;
    if (idx >= tot) return;
    int l = idx / (2 * DIM * DIM);
    int rem = idx % (2 * DIM * DIM);
    {
        int n = rem / DIM, k = rem % DIM;
        w1[idx] = __float2half_rn(W1[(size_t)l * DIM * 2 * DIM + (size_t)k * 2 * DIM + n]);
    }
    {
        int n2 = rem / (2 * DIM), k2 = rem % (2 * DIM);
        w2[idx] = __float2half_rn(W2[(size_t)l * 2 * DIM * DIM + (size_t)k2 * DIM + n2]);
    }
}

// ---------------------------------------------------------------------------
// CSR build: zero counts -> histogram -> scan (also writes cursor) -> fill
// ---------------------------------------------------------------------------
__global__ void zero_cnt_kernel(int* __restrict__ cnt, int n)
{
    int i = blockIdx.x * blockDim.x + threadIdx.x;
    if (i < n) cnt[i] = 0;
}
__global__ void hist_kernel(const int* __restrict__ dst, int* __restrict__ cnt, int E)
{
    int e = blockIdx.x * blockDim.x + threadIdx.x;
    if (e < E) atomicAdd(&cnt[dst[e] + 1], 1);
}
__global__ void scan_kernel(int* __restrict__ cnt, int* __restrict__ cur, int n1)
{
    __shared__ int wsum[32];
    __shared__ int carry;
    int tid = threadIdx.x, lane = tid & 31, wid = tid >> 5;
    if (tid == 0) carry = 0;
    __syncthreads();
    for (int base = 0; base < n1; base += 1024) {
        int i = base + tid;
        int v = (i < n1) ? cnt[i] : 0;
        int s = v;
#pragma unroll
        for (int o = 1; o < 32; o <<= 1) {
            int t = __shfl_up_sync(0xffffffffu, s, o);
            if (lane >= o) s += t;
        }
        if (lane == 31) wsum[wid] = s;
        __syncthreads();
        if (wid == 0) {
            int w = wsum[lane];
#pragma unroll
            for (int o = 1; o < 32; o <<= 1) {
                int t = __shfl_up_sync(0xffffffffu, w, o);
                if (lane >= o) w += t;
            }
            wsum[lane] = w;
        }
        __syncthreads();
        int inc = s + (wid ? wsum[wid - 1] : 0) + carry;
        if (i < n1) {
            cnt[i] = inc;
            if (i < n1 - 1) cur[i] = inc;   // cursor[i] = rowptr[i]
        }
        __syncthreads();
        if (tid == 1023) carry = inc;
        __syncthreads();
    }
}
__global__ void fill_kernel(const int* __restrict__ src, const int* __restrict__ dst,
                            int* __restrict__ cur, int* __restrict__ adj, int E)
{
    int e = blockIdx.x * blockDim.x + threadIdx.x;
    if (e < E) {
        int pos = atomicAdd(&cur[dst[e]], 1);
        adj[pos] = src[e];
    }
}

// ---------------------------------------------------------------------------
// Gather (fp16 h) + GIN combine + fp16 split
// one warp per node, lane covers 4 dims (uint2 = 4 halves)
// ---------------------------------------------------------------------------
__global__ __launch_bounds__(256)
void gather_kernel(const __half* __restrict__ h, const int* __restrict__ rowptr,
                   const int* __restrict__ adj, const float* __restrict__ epsp,
                   __half* __restrict__ chi, __half* __restrict__ clo, int N)
{
    int node = blockIdx.x * 8 + (threadIdx.x >> 5);
    int lane = threadIdx.x & 31;
    if (node >= N) return;

    int beg = rowptr[node], end = rowptr[node + 1];
    float4 s0 = make_float4(0.f, 0.f, 0.f, 0.f);
    float4 s1 = make_float4(0.f, 0.f, 0.f, 0.f);

    for (int e = beg; e < end; e += 32) {
        int a = (e + lane < end) ? __ldg(adj + e + lane) : -1;
        int cnt = min(32, end - e);
        int j = 0;
        for (; j + 1 < cnt; j += 2) {
            int n0 = __shfl_sync(0xffffffffu, a, j);
            int n1 = __shfl_sync(0xffffffffu, a, j + 1);
            uint2 r0 = __ldg((const uint2*)(h + (size_t)n0 * DIM) + lane);
            uint2 r1 = __ldg((const uint2*)(h + (size_t)n1 * DIM) + lane);
            float2 a01 = __half22float2(*(__half2*)&r0.x);
            float2 a23 = __half22float2(*(__half2*)&r0.y);
            float2 b01 = __half22float2(*(__half2*)&r1.x);
            float2 b23 = __half22float2(*(__half2*)&r1.y);
            s0.x += a01.x; s0.y += a01.y; s0.z += a23.x; s0.w += a23.y;
            s1.x += b01.x; s1.y += b01.y; s1.z += b23.x; s1.w += b23.y;
        }
        if (j < cnt) {
            int n0 = __shfl_sync(0xffffffffu, a, j);
            uint2 r0 = __ldg((const uint2*)(h + (size_t)n0 * DIM) + lane);
            float2 a01 = __half22float2(*(__half2*)&r0.x);
            float2 a23 = __half22float2(*(__half2*)&r0.y);
            s0.x += a01.x; s0.y += a01.y; s0.z += a23.x; s0.w += a23.y;
        }
    }

    float epsv = 1.0f + epsp[0];
    uint2 hraw = __ldg((const uint2*)(h + (size_t)node * DIM) + lane);
    float2 h01 = __half22float2(*(__half2*)&hraw.x);
    float2 h23 = __half22float2(*(__half2*)&hraw.y);
    float4 c;
    c.x = fmaf(epsv, h01.x, s0.x + s1.x);
    c.y = fmaf(epsv, h01.y, s0.y + s1.y);
    c.z = fmaf(epsv, h23.x, s0.z + s1.z);
    c.w = fmaf(epsv, h23.y, s0.w + s1.w);

    uint32_t p01, q01, p23, q23;
    split2h(c.x, c.y, p01, q01);
    split2h(c.z, c.w, p23, q23);
    uint2* ph = (uint2*)(chi + (size_t)node * DIM) + lane;
    uint2* pl = (uint2*)(clo + (size_t)node * DIM) + lane;
    *ph = make_uint2(p01, p23);
    *pl = make_uint2(q01, q23);
}

// ---------------------------------------------------------------------------
// 2xFP16 mma.sync GEMM: C = act(bn((Ahi+Alo) @ W + bias)),  W fp16 single.
//   block 128x128, 8 warps (2M x 4N), warp tile 64x32, BK=32 double-buffered.
//   Output: fp32 (Cf), split fp16 (Chi/Clo), or single fp16 (Ch).
// ---------------------------------------------------------------------------
#define BK 32
#define ASTRIDE 40                 // fp16 per smem row (80 B, conflict-free)
#define ABUF_B (128 * ASTRIDE * 2) // 10240 B per buffer
#define STAGE_B (3 * ABUF_B)       // Ahi, Alo, W

__global__ __launch_bounds__(256)
void gemm_mma_kernel(const __half* __restrict__ Ahi, const __half* __restrict__ Alo,
                     const __half* __restrict__ W,
                     const float* __restrict__ bias, const float* __restrict__ bns,
                     const float* __restrict__ bnt,
                     float* __restrict__ Cf, __half* __restrict__ Chi,
                     __half* __restrict__ Clo, __half* __restrict__ Ch,
                     int M, int K, int Nc, int relu)
{
    extern __shared__ char smem[];
    const int tid = threadIdx.x;
    const int lane = tid & 31, wid = tid >> 5;
    const int warpM = wid >> 2, warpN = wid & 3;
    const int rowBase = blockIdx.y * 128;
    const int colBase = blockIdx.x * 128;
    const uint32_t sbase = smem_to_u32(smem);

    float acc[4][4][4];
#pragma unroll
    for (int a = 0; a < 4; a++)
#pragma unroll
        for (int b = 0; b < 4; b++)
#pragma unroll
            for (int c = 0; c < 4; c++) acc[a][b][c] = 0.f;

    const int frow = lane & 15, fk = (lane >> 4) * 8;
    uint32_t offA[4], offB[2];
#pragma unroll
    for (int mf = 0; mf < 4; mf++)
        offA[mf] = ((warpM * 64 + mf * 16 + frow) * ASTRIDE + fk) * 2;
#pragma unroll
    for (int nb = 0; nb < 2; nb++)
        offB[nb] = ((warpN * 32 + nb * 16 + frow) * ASTRIDE + fk) * 2;

    const int nch = K / BK;

    uint64_t pah[4], pal[4], pw[4];

    // ---- prefetch chunk 0 ----
#pragma unroll
    for (int i = 0; i < 4; i++) {
        int f = tid + i * 256;
        int r = f >> 3, q = f & 7;
        int g = rowBase + r;
        if (g < M) {
            pah[i] = __ldg((const uint64_t*)(Ahi + (size_t)g * K) + q);
            pal[i] = __ldg((const uint64_t*)(Alo + (size_t)g * K) + q);
        } else { pah[i] = 0; pal[i] = 0; }
        pw[i] = __ldg((const uint64_t*)(W + (size_t)(colBase + r) * K) + q);
    }

    int s = 0;
    for (int c = 0; c < nch; c++) {
        // ---- store prefetched regs into stage s ----
        {
            char* Ahi_s = smem + s * STAGE_B;
            char* Alo_s = Ahi_s + ABUF_B;
            char* W_s   = Ahi_s + 2 * ABUF_B;
#pragma unroll
            for (int i = 0; i < 4; i++) {
                int f = tid + i * 256;
                int r = f >> 3, q = f & 7;
                int so = r * (ASTRIDE * 2) + q * 8;
                *(uint64_t*)(Ahi_s + so) = pah[i];
                *(uint64_t*)(Alo_s + so) = pal[i];
                *(uint64_t*)(W_s   + so) = pw[i];
            }
        }
        __syncthreads();

        // ---- prefetch next chunk ----
        if (c + 1 < nch) {
            int k0 = (c + 1) * BK;
#pragma unroll
            for (int i = 0; i < 4; i++) {
                int f = tid + i * 256;
                int r = f >> 3, q = f & 7;
                int g = rowBase + r;
                if (g < M) {
                    pah[i] = __ldg((const uint64_t*)(Ahi + (size_t)g * K + k0) + q);
                    pal[i] = __ldg((const uint64_t*)(Alo + (size_t)g * K + k0) + q);
                } else { pah[i] = 0; pal[i] = 0; }
                pw[i] = __ldg((const uint64_t*)(W + (size_t)(colBase + r) * K + k0) + q);
            }
        }

        // ---- mma over stage s: 2 k16 steps ----
        uint32_t bufA_hi = sbase + s * STAGE_B;
        uint32_t bufA_lo = bufA_hi + ABUF_B;
        uint32_t bufW    = bufA_hi + 2 * ABUF_B;
#pragma unroll
        for (int ks = 0; ks < 2; ks++) {
            uint32_t ah[4][4], al[4][4], bw[2][4];
#pragma unroll
            for (int mf = 0; mf < 4; mf++) {
                ldmx4(ah[mf], bufA_hi + offA[mf] + ks * 32);
                ldmx4(al[mf], bufA_lo + offA[mf] + ks * 32);
            }
#pragma unroll
            for (int nb = 0; nb < 2; nb++)
                ldmx4(bw[nb], bufW + offB[nb] + ks * 32);
#pragma unroll
            for (int mf = 0; mf < 4; mf++) {
#pragma unroll
                for (int nf = 0; nf < 4; nf++) {
                    int nb = nf >> 1, sel = nf & 1;
                    uint32_t b0 = bw[nb][sel], b1 = bw[nb][sel + 2];
                    mma_f16(acc[mf][nf], ah[mf], b0, b1);
                    mma_f16(acc[mf][nf], al[mf], b0, b1);
                }
            }
        }
        __syncthreads();
        s ^= 1;
    }

    // ---- epilogue ----
    const int g = lane >> 2, tig = lane & 3;
    float bj0[4], bj1[4], sj0[4], sj1[4], tj0[4], tj1[4];
#pragma unroll
    for (int nf = 0; nf < 4; nf++) {
        int col = colBase + warpN * 32 + nf * 8 + 2 * tig;
        bj0[nf] = bias[col];
        bj1[nf] = bias[col + 1];
        if (bns) {
            sj0[nf] = bns[col];  sj1[nf] = bns[col + 1];
            tj0[nf] = bnt[col];  tj1[nf] = bnt[col + 1];
        }
    }
#pragma unroll
    for (int mf = 0; mf < 4; mf++) {
#pragma unroll
        for (int half = 0; half < 2; half++) {
            int row = rowBase + warpM * 64 + mf * 16 + g + half * 8;
            if (row >= M) continue;
#pragma unroll
            for (int nf = 0; nf < 4; nf++) {
                int col = colBase + warpN * 32 + nf * 8 + 2 * tig;
                float v0 = acc[mf][nf][half * 2 + 0] + bj0[nf];
                float v1 = acc[mf][nf][half * 2 + 1] + bj1[nf];
                if (bns) {
                    v0 = fmaf(v0, sj0[nf], tj0[nf]);
                    v1 = fmaf(v1, sj1[nf], tj1[nf]);
                }
                if (relu) { v0 = fmaxf(v0, 0.f); v1 = fmaxf(v1, 0.f); }
                if (Cf) {
                    *(float2*)(Cf + (size_t)row * Nc + col) = make_float2(v0, v1);
                } else if (Chi) {
                    uint32_t hi, lo;
                    split2h(v0, v1, hi, lo);
                    *(uint32_t*)(Chi + (size_t)row * Nc + col) = hi;
                    *(uint32_t*)(Clo + (size_t)row * Nc + col) = lo;
                } else {
                    __half2 p = __floats2half2_rn(v0, v1);
                    *(uint32_t*)(Ch + (size_t)row * Nc + col) = *(uint32_t*)&p;
                }
            }
        }
    }
}

// ---------------------------------------------------------------------------
// log_softmax: one warp per row, lane covers 4 cols
// ---------------------------------------------------------------------------
__global__ __launch_bounds__(128)
void logsoftmax_kernel(float* __restrict__ C, int N)
{
    int row = blockIdx.x * 4 + (threadIdx.x >> 5);
    int lane = threadIdx.x & 31;
    if (row >= N) return;
    float4 v = *((const float4*)(C + (size_t)row * DIM) + lane);
    float m = fmaxf(fmaxf(v.x, v.y), fmaxf(v.z, v.w));
#pragma unroll
    for (int o = 16; o > 0; o >>= 1)
        m = fmaxf(m, __shfl_xor_sync(0xffffffffu, m, o));
    float e = expf(v.x - m) + expf(v.y - m) + expf(v.z - m) + expf(v.w - m);
#pragma unroll
    for (int o = 16; o > 0; o >>= 1)
        e += __shfl_xor_sync(0xffffffffu, e, o);
    float lse = m + logf(e);
    v.x -= lse; v.y -= lse; v.z -= lse; v.w -= lse;
    *((float4*)(C + (size_t)row * DIM) + lane) = v;
}

// ---------------------------------------------------------------------------
extern "C" void kernel_launch(void* const* d_in, const int* in_sizes, int n_in,
                              void* d_out, int out_size)
{
    const float* x    = (const float*)d_in[0];
    const int*   ei   = (const int*)  d_in[1];
    const float* W1   = (const float*)d_in[2];
    const float* b1   = (const float*)d_in[3];
    const float* g1   = (const float*)d_in[4];
    const float* be1  = (const float*)d_in[5];
    const float* m1   = (const float*)d_in[6];
    const float* v1   = (const float*)d_in[7];
    const float* W2   = (const float*)d_in[8];
    const float* b2   = (const float*)d_in[9];
    const float* eps  = (const float*)d_in[10];
    const float* go   = (const float*)d_in[11];
    const float* bo   = (const float*)d_in[12];
    const float* mo   = (const float*)d_in[13];
    const float* vo   = (const float*)d_in[14];

    int N = in_sizes[0] / DIM;
    int E = in_sizes[1] / 2;

    float *s1, *t1, *so, *to;
    __half *hh, *chi, *clo, *zhi, *zlo, *w1, *w2;
    int *rowptr, *cursor, *adj;
    cudaGetSymbolAddress((void**)&hh,     g_hh);
    cudaGetSymbolAddress((void**)&chi,    g_chi);
    cudaGetSymbolAddress((void**)&clo,    g_clo);
    cudaGetSymbolAddress((void**)&zhi,    g_zhi);
    cudaGetSymbolAddress((void**)&zlo,    g_zlo);
    cudaGetSymbolAddress((void**)&s1,     g_s1);
    cudaGetSymbolAddress((void**)&t1,     g_t1);
    cudaGetSymbolAddress((void**)&so,     g_so);
    cudaGetSymbolAddress((void**)&to,     g_to);
    cudaGetSymbolAddress((void**)&w1,     g_w1);
    cudaGetSymbolAddress((void**)&w2,     g_w2);
    cudaGetSymbolAddress((void**)&rowptr, g_rowptr);
    cudaGetSymbolAddress((void**)&cursor, g_cursor);
    cudaGetSymbolAddress((void**)&adj,    g_adj);

    const int dynSmem = 2 * STAGE_B;  // 61440 B
    cudaFuncSetAttribute(gemm_mma_kernel, cudaFuncAttributeMaxDynamicSharedMemorySize, dynSmem);

    const int* src = ei;
    const int* dst = ei + E;

    // ---- setup: BN folding, x/weight conversion, CSR build ----
    bn_pre_kernel<<<1, LNUM * 2 * DIM>>>(g1, be1, m1, v1, go, bo, mo, vo, s1, t1, so, to);
    xconv_kernel<<<(N * DIM / 2 + 255) / 256, 256>>>(x, hh, N * DIM / 2);
    {
        int tot = LNUM * 2 * DIM * DIM;
        wconv_kernel<<<(tot + 255) / 256, 256>>>(W1, W2, w1, w2);
    }
    zero_cnt_kernel<<<(N + 1 + 255) / 256, 256>>>(rowptr, N + 1);
    hist_kernel<<<(E + 255) / 256, 256>>>(dst, rowptr, E);
    scan_kernel<<<1, 1024>>>(rowptr, cursor, N + 1);
    fill_kernel<<<(E + 255) / 256, 256>>>(src, dst, cursor, adj, E);

    int mblocks = (N + 127) / 128;
    int gblocks = (N + 7) / 8;

    for (int i = 0; i < LNUM; i++) {
        // gather + combine + split -> chi/clo [N,128]
        gather_kernel<<<gblocks, 256>>>(hh, rowptr, adj, eps + i, chi, clo, N);

        // GEMM1: z[N,256] = combine @ W1 -> bias, BN, ReLU -> split zhi/zlo
        dim3 grid1(2, mblocks);
        gemm_mma_kernel<<<grid1, 256, dynSmem>>>(chi, clo,
                                                 w1 + (size_t)i * 2 * DIM * DIM,
                                                 b1 + (size_t)i * 2 * DIM,
                                                 s1 + (size_t)i * 2 * DIM,
                                                 t1 + (size_t)i * 2 * DIM,
                                                 nullptr, zhi, zlo, nullptr,
                                                 N, DIM, 2 * DIM, 1);

        dim3 grid2(1, mblocks);
        if (i < LNUM - 1) {
            // GEMM2: h[N,128] fp16 = z @ W2 -> bias, BN, ReLU
            gemm_mma_kernel<<<grid2, 256, dynSmem>>>(zhi, zlo,
                                                     w2 + (size_t)i * 2 * DIM * DIM,
                                                     b2 + (size_t)i * DIM,
                                                     so + (size_t)i * DIM,
                                                     to + (size_t)i * DIM,
                                                     nullptr, nullptr, nullptr, hh,
                                                     N, 2 * DIM, DIM, 1);
        } else {
            gemm_mma_kernel<<<grid2, 256, dynSmem>>>(zhi, zlo,
                                                     w2 + (size_t)i * 2 * DIM * DIM,
                                                     b2 + (size_t)i * DIM,
                                                     nullptr, nullptr,
                                                     (float*)d_out, nullptr, nullptr, nullptr,
                                                     N, 2 * DIM, DIM, 0);
        }
    }

    logsoftmax_kernel<<<(N + 3) / 4, 128>>>((float*)d_out, N);
}

// round 8
// speedup vs baseline: 5.0071x; 1.3231x over previous
#include <cuda_runtime.h>
#include <cuda_fp16.h>
#include <cstdint>
#include <math.h>

#define NMAX 50000
#define EMAX 800000
#define DIM  128
#define LNUM 3

// ---------------------------------------------------------------------------
// scratch (no allocation allowed)
// ---------------------------------------------------------------------------
__device__ __half g_hh [(size_t)NMAX * DIM];        // fp16 activations between layers (and x)
__device__ __half g_c  [(size_t)NMAX * DIM];        // GIN combine (GEMM1 input)
__device__ __half g_z  [(size_t)NMAX * 2 * DIM];    // z (GEMM2 input)
__device__ float g_s1[LNUM * 2 * DIM];
__device__ float g_t1[LNUM * 2 * DIM];
__device__ float g_so[(LNUM - 1) * DIM];
__device__ float g_to[(LNUM - 1) * DIM];
// transposed fp16 weights: W1T [L][256][128], W2T [L][128][256]
__device__ __half g_w1[LNUM * 2 * DIM * DIM];
__device__ __half g_w2[LNUM * 2 * DIM * DIM];
// CSR
__device__ int g_rowptr[NMAX + 1];
__device__ int g_cursor[NMAX];
__device__ int g_adj[EMAX];

// ---------------------------------------------------------------------------
// helpers
// ---------------------------------------------------------------------------
__device__ __forceinline__ uint32_t smem_to_u32(const void* p) {
    uint32_t a;
    asm("{ .reg .u64 t; cvta.to.shared.u64 t, %1; cvt.u32.u64 %0, t; }" : "=r"(a) : "l"(p));
    return a;
}
__device__ __forceinline__ void ldmx4(uint32_t* r, uint32_t addr) {
    asm volatile("ldmatrix.sync.aligned.m8n8.x4.shared.b16 {%0,%1,%2,%3}, [%4];"
                 : "=r"(r[0]), "=r"(r[1]), "=r"(r[2]), "=r"(r[3]) : "r"(addr));
}
__device__ __forceinline__ void mma_f16(float* c, const uint32_t* a, uint32_t b0, uint32_t b1) {
    asm volatile("mma.sync.aligned.m16n8k16.row.col.f32.f16.f16.f32 "
                 "{%0,%1,%2,%3}, {%4,%5,%6,%7}, {%8,%9}, {%0,%1,%2,%3};"
                 : "+f"(c[0]), "+f"(c[1]), "+f"(c[2]), "+f"(c[3])
                 : "r"(a[0]), "r"(a[1]), "r"(a[2]), "r"(a[3]), "r"(b0), "r"(b1));
}

// ---------------------------------------------------------------------------
// BN precompute
// ---------------------------------------------------------------------------
__global__ void bn_pre_kernel(const float* __restrict__ g1, const float* __restrict__ be1,
                              const float* __restrict__ m1, const float* __restrict__ v1,
                              const float* __restrict__ go, const float* __restrict__ bo,
                              const float* __restrict__ mo, const float* __restrict__ vo,
                              float* __restrict__ s1, float* __restrict__ t1,
                              float* __restrict__ so, float* __restrict__ to)
{
    int t = blockIdx.x * blockDim.x + threadIdx.x;
    if (t < LNUM * 2 * DIM) {
        float sc = g1[t] * rsqrtf(v1[t] + 1e-5f);
        s1[t] = sc;
        t1[t] = be1[t] - m1[t] * sc;
    }
    if (t < (LNUM - 1) * DIM) {
        float sc = go[t] * rsqrtf(vo[t] + 1e-5f);
        so[t] = sc;
        to[t] = bo[t] - mo[t] * sc;
    }
}

// ---------------------------------------------------------------------------
// x -> fp16 pre-convert
// ---------------------------------------------------------------------------
__global__ void xconv_kernel(const float* __restrict__ x, __half* __restrict__ xh, int n)
{
    int i = blockIdx.x * blockDim.x + threadIdx.x;
    if (i < n) {
        float2 v = *((const float2*)x + i);
        __half2 p = __floats2half2_rn(v.x, v.y);
        *((__half2*)xh + i) = p;
    }
}

// ---------------------------------------------------------------------------
// Weight transpose + fp16 round.
// ---------------------------------------------------------------------------
__global__ void wconv_kernel(const float* __restrict__ W1, const float* __restrict__ W2,
                             __half* __restrict__ w1, __half* __restrict__ w2)
{
    int idx = blockIdx.x * blockDim.x + threadIdx.x;
    const int tot = LNUM * 2 * DIM * DIM;
    if (idx >= tot) return;
    int l = idx / (2 * DIM * DIM);
    int rem = idx % (2 * DIM * DIM);
    {
        int n = rem / DIM, k = rem % DIM;
        w1[idx] = __float2half_rn(W1[(size_t)l * DIM * 2 * DIM + (size_t)k * 2 * DIM + n]);
    }
    {
        int n2 = rem / (2 * DIM), k2 = rem % (2 * DIM);
        w2[idx] = __float2half_rn(W2[(size_t)l * 2 * DIM * DIM + (size_t)k2 * DIM + n2]);
    }
}

// ---------------------------------------------------------------------------
// CSR build: zero counts -> histogram -> scan (also writes cursor) -> fill
// ---------------------------------------------------------------------------
__global__ void zero_cnt_kernel(int* __restrict__ cnt, int n)
{
    int i = blockIdx.x * blockDim.x + threadIdx.x;
    if (i < n) cnt[i] = 0;
}
__global__ void hist_kernel(const int* __restrict__ dst, int* __restrict__ cnt, int E)
{
    int e = blockIdx.x * blockDim.x + threadIdx.x;
    if (e < E) atomicAdd(&cnt[dst[e] + 1], 1);
}
__global__ void scan_kernel(int* __restrict__ cnt, int* __restrict__ cur, int n1)
{
    __shared__ int wsum[32];
    __shared__ int carry;
    int tid = threadIdx.x, lane = tid & 31, wid = tid >> 5;
    if (tid == 0) carry = 0;
    __syncthreads();
    for (int base = 0; base < n1; base += 1024) {
        int i = base + tid;
        int v = (i < n1) ? cnt[i] : 0;
        int s = v;
#pragma unroll
        for (int o = 1; o < 32; o <<= 1) {
            int t = __shfl_up_sync(0xffffffffu, s, o);
            if (lane >= o) s += t;
        }
        if (lane == 31) wsum[wid] = s;
        __syncthreads();
        if (wid == 0) {
            int w = wsum[lane];
#pragma unroll
            for (int o = 1; o < 32; o <<= 1) {
                int t = __shfl_up_sync(0xffffffffu, w, o);
                if (lane >= o) w += t;
            }
            wsum[lane] = w;
        }
        __syncthreads();
        int inc = s + (wid ? wsum[wid - 1] : 0) + carry;
        if (i < n1) {
            cnt[i] = inc;
            if (i < n1 - 1) cur[i] = inc;   // cursor[i] = rowptr[i]
        }
        __syncthreads();
        if (tid == 1023) carry = inc;
        __syncthreads();
    }
}
__global__ void fill_kernel(const int* __restrict__ src, const int* __restrict__ dst,
                            int* __restrict__ cur, int* __restrict__ adj, int E)
{
    int e = blockIdx.x * blockDim.x + threadIdx.x;
    if (e < E) {
        int pos = atomicAdd(&cur[dst[e]], 1);
        adj[pos] = src[e];
    }
}

// ---------------------------------------------------------------------------
// Gather (fp16 h) + GIN combine -> single fp16 buffer
// one warp per node, lane covers 4 dims (uint2 = 4 halves)
// ---------------------------------------------------------------------------
__global__ __launch_bounds__(256)
void gather_kernel(const __half* __restrict__ h, const int* __restrict__ rowptr,
                   const int* __restrict__ adj, const float* __restrict__ epsp,
                   __half* __restrict__ cbuf, int N)
{
    int node = blockIdx.x * 8 + (threadIdx.x >> 5);
    int lane = threadIdx.x & 31;
    if (node >= N) return;

    int beg = rowptr[node], end = rowptr[node + 1];
    float4 s0 = make_float4(0.f, 0.f, 0.f, 0.f);
    float4 s1 = make_float4(0.f, 0.f, 0.f, 0.f);

    for (int e = beg; e < end; e += 32) {
        int a = (e + lane < end) ? __ldg(adj + e + lane) : -1;
        int cnt = min(32, end - e);
        int j = 0;
        for (; j + 1 < cnt; j += 2) {
            int n0 = __shfl_sync(0xffffffffu, a, j);
            int n1 = __shfl_sync(0xffffffffu, a, j + 1);
            uint2 r0 = __ldg((const uint2*)(h + (size_t)n0 * DIM) + lane);
            uint2 r1 = __ldg((const uint2*)(h + (size_t)n1 * DIM) + lane);
            float2 a01 = __half22float2(*(__half2*)&r0.x);
            float2 a23 = __half22float2(*(__half2*)&r0.y);
            float2 b01 = __half22float2(*(__half2*)&r1.x);
            float2 b23 = __half22float2(*(__half2*)&r1.y);
            s0.x += a01.x; s0.y += a01.y; s0.z += a23.x; s0.w += a23.y;
            s1.x += b01.x; s1.y += b01.y; s1.z += b23.x; s1.w += b23.y;
        }
        if (j < cnt) {
            int n0 = __shfl_sync(0xffffffffu, a, j);
            uint2 r0 = __ldg((const uint2*)(h + (size_t)n0 * DIM) + lane);
            float2 a01 = __half22float2(*(__half2*)&r0.x);
            float2 a23 = __half22float2(*(__half2*)&r0.y);
            s0.x += a01.x; s0.y += a01.y; s0.z += a23.x; s0.w += a23.y;
        }
    }

    float epsv = 1.0f + epsp[0];
    uint2 hraw = __ldg((const uint2*)(h + (size_t)node * DIM) + lane);
    float2 h01 = __half22float2(*(__half2*)&hraw.x);
    float2 h23 = __half22float2(*(__half2*)&hraw.y);
    __half2 c01 = __floats2half2_rn(fmaf(epsv, h01.x, s0.x + s1.x),
                                    fmaf(epsv, h01.y, s0.y + s1.y));
    __half2 c23 = __floats2half2_rn(fmaf(epsv, h23.x, s0.z + s1.z),
                                    fmaf(epsv, h23.y, s0.w + s1.w));
    uint2 outp = make_uint2(*(uint32_t*)&c01, *(uint32_t*)&c23);
    *((uint2*)(cbuf + (size_t)node * DIM) + lane) = outp;
}

// ---------------------------------------------------------------------------
// FP16 mma.sync GEMM: C = act(bn(A @ W + bias)); optional fused log_softmax.
//   block 128x128, 8 warps (2M x 4N), warp tile 64x32, BK=32 double-buffered.
//   Output: fp32 (Cf, + dosm=fused log_softmax when grid.x==1) or fp16 (Ch).
// ---------------------------------------------------------------------------
#define BK 32
#define ASTRIDE 40                 // fp16 per smem row (80 B, conflict-free)
#define ABUF_B (128 * ASTRIDE * 2) // 10240 B per buffer
#define STAGE_B (2 * ABUF_B)       // A, W

__global__ __launch_bounds__(256)
void gemm_mma_kernel(const __half* __restrict__ A, const __half* __restrict__ W,
                     const float* __restrict__ bias, const float* __restrict__ bns,
                     const float* __restrict__ bnt,
                     float* __restrict__ Cf, __half* __restrict__ Ch,
                     int M, int K, int Nc, int relu, int dosm)
{
    extern __shared__ char smem[];
    __shared__ float smax[128][4];
    __shared__ float ssum[128][4];
    const int tid = threadIdx.x;
    const int lane = tid & 31, wid = tid >> 5;
    const int warpM = wid >> 2, warpN = wid & 3;
    const int rowBase = blockIdx.y * 128;
    const int colBase = blockIdx.x * 128;
    const uint32_t sbase = smem_to_u32(smem);

    float acc[4][4][4];
#pragma unroll
    for (int a = 0; a < 4; a++)
#pragma unroll
        for (int b = 0; b < 4; b++)
#pragma unroll
            for (int c = 0; c < 4; c++) acc[a][b][c] = 0.f;

    const int frow = lane & 15, fk = (lane >> 4) * 8;
    uint32_t offA[4], offB[2];
#pragma unroll
    for (int mf = 0; mf < 4; mf++)
        offA[mf] = ((warpM * 64 + mf * 16 + frow) * ASTRIDE + fk) * 2;
#pragma unroll
    for (int nb = 0; nb < 2; nb++)
        offB[nb] = ((warpN * 32 + nb * 16 + frow) * ASTRIDE + fk) * 2;

    const int nch = K / BK;
    uint64_t pa[4], pw[4];

    // ---- prefetch chunk 0 ----
#pragma unroll
    for (int i = 0; i < 4; i++) {
        int f = tid + i * 256;
        int r = f >> 3, q = f & 7;
        int g = rowBase + r;
        pa[i] = (g < M) ? __ldg((const uint64_t*)(A + (size_t)g * K) + q) : 0ull;
        pw[i] = __ldg((const uint64_t*)(W + (size_t)(colBase + r) * K) + q);
    }

    int s = 0;
    for (int c = 0; c < nch; c++) {
        {
            char* A_s = smem + s * STAGE_B;
            char* W_s = A_s + ABUF_B;
#pragma unroll
            for (int i = 0; i < 4; i++) {
                int f = tid + i * 256;
                int r = f >> 3, q = f & 7;
                int so = r * (ASTRIDE * 2) + q * 8;
                *(uint64_t*)(A_s + so) = pa[i];
                *(uint64_t*)(W_s + so) = pw[i];
            }
        }
        __syncthreads();

        if (c + 1 < nch) {
            int k0 = (c + 1) * BK;
#pragma unroll
            for (int i = 0; i < 4; i++) {
                int f = tid + i * 256;
                int r = f >> 3, q = f & 7;
                int g = rowBase + r;
                pa[i] = (g < M) ? __ldg((const uint64_t*)(A + (size_t)g * K + k0) + q) : 0ull;
                pw[i] = __ldg((const uint64_t*)(W + (size_t)(colBase + r) * K + k0) + q);
            }
        }

        uint32_t bufA = sbase + s * STAGE_B;
        uint32_t bufW = bufA + ABUF_B;
#pragma unroll
        for (int ks = 0; ks < 2; ks++) {
            uint32_t ar[4][4], bw[2][4];
#pragma unroll
            for (int mf = 0; mf < 4; mf++)
                ldmx4(ar[mf], bufA + offA[mf] + ks * 32);
#pragma unroll
            for (int nb = 0; nb < 2; nb++)
                ldmx4(bw[nb], bufW + offB[nb] + ks * 32);
#pragma unroll
            for (int mf = 0; mf < 4; mf++) {
#pragma unroll
                for (int nf = 0; nf < 4; nf++) {
                    int nb = nf >> 1, sel = nf & 1;
                    mma_f16(acc[mf][nf], ar[mf], bw[nb][sel], bw[nb][sel + 2]);
                }
            }
        }
        __syncthreads();
        s ^= 1;
    }

    // ---- epilogue ----
    const int g = lane >> 2, tig = lane & 3;
    float bj0[4], bj1[4], sj0[4], sj1[4], tj0[4], tj1[4];
#pragma unroll
    for (int nf = 0; nf < 4; nf++) {
        int col = colBase + warpN * 32 + nf * 8 + 2 * tig;
        bj0[nf] = bias[col];
        bj1[nf] = bias[col + 1];
        if (bns) {
            sj0[nf] = bns[col];  sj1[nf] = bns[col + 1];
            tj0[nf] = bnt[col];  tj1[nf] = bnt[col + 1];
        }
    }
    // transform acc in place: bias (+BN,ReLU)
#pragma unroll
    for (int mf = 0; mf < 4; mf++)
#pragma unroll
        for (int nf = 0; nf < 4; nf++)
#pragma unroll
            for (int half = 0; half < 2; half++) {
                float v0 = acc[mf][nf][half * 2 + 0] + bj0[nf];
                float v1 = acc[mf][nf][half * 2 + 1] + bj1[nf];
                if (bns) {
                    v0 = fmaf(v0, sj0[nf], tj0[nf]);
                    v1 = fmaf(v1, sj1[nf], tj1[nf]);
                }
                if (relu) { v0 = fmaxf(v0, 0.f); v1 = fmaxf(v1, 0.f); }
                acc[mf][nf][half * 2 + 0] = v0;
                acc[mf][nf][half * 2 + 1] = v1;
            }

    if (dosm) {
        // fused log_softmax: all 128 cols of each row live in this block
        float rowmax[4][2];
#pragma unroll
        for (int mf = 0; mf < 4; mf++)
#pragma unroll
            for (int half = 0; half < 2; half++) {
                float mx = -1e30f;
#pragma unroll
                for (int nf = 0; nf < 4; nf++) {
                    mx = fmaxf(mx, acc[mf][nf][half * 2 + 0]);
                    mx = fmaxf(mx, acc[mf][nf][half * 2 + 1]);
                }
                mx = fmaxf(mx, __shfl_xor_sync(0xffffffffu, mx, 1));
                mx = fmaxf(mx, __shfl_xor_sync(0xffffffffu, mx, 2));
                int row = warpM * 64 + mf * 16 + g + half * 8;
                if (tig == 0) smax[row][warpN] = mx;
            }
        __syncthreads();
#pragma unroll
        for (int mf = 0; mf < 4; mf++)
#pragma unroll
            for (int half = 0; half < 2; half++) {
                int row = warpM * 64 + mf * 16 + g + half * 8;
                float mx = fmaxf(fmaxf(smax[row][0], smax[row][1]),
                                 fmaxf(smax[row][2], smax[row][3]));
                rowmax[mf][half] = mx;
                float se = 0.f;
#pragma unroll
                for (int nf = 0; nf < 4; nf++) {
                    se += expf(acc[mf][nf][half * 2 + 0] - mx);
                    se += expf(acc[mf][nf][half * 2 + 1] - mx);
                }
                se += __shfl_xor_sync(0xffffffffu, se, 1);
                se += __shfl_xor_sync(0xffffffffu, se, 2);
                if (tig == 0) ssum[row][warpN] = se;
            }
        __syncthreads();
#pragma unroll
        for (int mf = 0; mf < 4; mf++)
#pragma unroll
            for (int half = 0; half < 2; half++) {
                int row = warpM * 64 + mf * 16 + g + half * 8;
                int grow = rowBase + row;
                if (grow >= M) continue;
                float tot = ssum[row][0] + ssum[row][1] + ssum[row][2] + ssum[row][3];
                float lse = rowmax[mf][half] + logf(tot);
#pragma unroll
                for (int nf = 0; nf < 4; nf++) {
                    int col = colBase + warpN * 32 + nf * 8 + 2 * tig;
                    float2 o = make_float2(acc[mf][nf][half * 2 + 0] - lse,
                                           acc[mf][nf][half * 2 + 1] - lse);
                    *(float2*)(Cf + (size_t)grow * Nc + col) = o;
                }
            }
        return;
    }

#pragma unroll
    for (int mf = 0; mf < 4; mf++)
#pragma unroll
        for (int half = 0; half < 2; half++) {
            int row = rowBase + warpM * 64 + mf * 16 + g + half * 8;
            if (row >= M) continue;
#pragma unroll
            for (int nf = 0; nf < 4; nf++) {
                int col = colBase + warpN * 32 + nf * 8 + 2 * tig;
                float v0 = acc[mf][nf][half * 2 + 0];
                float v1 = acc[mf][nf][half * 2 + 1];
                if (Cf) {
                    *(float2*)(Cf + (size_t)row * Nc + col) = make_float2(v0, v1);
                } else {
                    __half2 p = __floats2half2_rn(v0, v1);
                    *(uint32_t*)(Ch + (size_t)row * Nc + col) = *(uint32_t*)&p;
                }
            }
        }
}

// ---------------------------------------------------------------------------
extern "C" void kernel_launch(void* const* d_in, const int* in_sizes, int n_in,
                              void* d_out, int out_size)
{
    const float* x    = (const float*)d_in[0];
    const int*   ei   = (const int*)  d_in[1];
    const float* W1   = (const float*)d_in[2];
    const float* b1   = (const float*)d_in[3];
    const float* g1   = (const float*)d_in[4];
    const float* be1  = (const float*)d_in[5];
    const float* m1   = (const float*)d_in[6];
    const float* v1   = (const float*)d_in[7];
    const float* W2   = (const float*)d_in[8];
    const float* b2   = (const float*)d_in[9];
    const float* eps  = (const float*)d_in[10];
    const float* go   = (const float*)d_in[11];
    const float* bo   = (const float*)d_in[12];
    const float* mo   = (const float*)d_in[13];
    const float* vo   = (const float*)d_in[14];

    int N = in_sizes[0] / DIM;
    int E = in_sizes[1] / 2;

    float *s1, *t1, *so, *to;
    __half *hh, *cb, *zb, *w1, *w2;
    int *rowptr, *cursor, *adj;
    cudaGetSymbolAddress((void**)&hh,     g_hh);
    cudaGetSymbolAddress((void**)&cb,     g_c);
    cudaGetSymbolAddress((void**)&zb,     g_z);
    cudaGetSymbolAddress((void**)&s1,     g_s1);
    cudaGetSymbolAddress((void**)&t1,     g_t1);
    cudaGetSymbolAddress((void**)&so,     g_so);
    cudaGetSymbolAddress((void**)&to,     g_to);
    cudaGetSymbolAddress((void**)&w1,     g_w1);
    cudaGetSymbolAddress((void**)&w2,     g_w2);
    cudaGetSymbolAddress((void**)&rowptr, g_rowptr);
    cudaGetSymbolAddress((void**)&cursor, g_cursor);
    cudaGetSymbolAddress((void**)&adj,    g_adj);

    const int dynSmem = 2 * STAGE_B;  // 40960 B
    cudaFuncSetAttribute(gemm_mma_kernel, cudaFuncAttributeMaxDynamicSharedMemorySize, dynSmem);

    const int* src = ei;
    const int* dst = ei + E;

    // ---- setup: BN folding, x/weight conversion, CSR build ----
    bn_pre_kernel<<<1, LNUM * 2 * DIM>>>(g1, be1, m1, v1, go, bo, mo, vo, s1, t1, so, to);
    xconv_kernel<<<(N * DIM / 2 + 255) / 256, 256>>>(x, hh, N * DIM / 2);
    {
        int tot = LNUM * 2 * DIM * DIM;
        wconv_kernel<<<(tot + 255) / 256, 256>>>(W1, W2, w1, w2);
    }
    zero_cnt_kernel<<<(N + 1 + 255) / 256, 256>>>(rowptr, N + 1);
    hist_kernel<<<(E + 255) / 256, 256>>>(dst, rowptr, E);
    scan_kernel<<<1, 1024>>>(rowptr, cursor, N + 1);
    fill_kernel<<<(E + 255) / 256, 256>>>(src, dst, cursor, adj, E);

    int mblocks = (N + 127) / 128;
    int gblocks = (N + 7) / 8;

    for (int i = 0; i < LNUM; i++) {
        // gather + combine -> cb [N,128] fp16
        gather_kernel<<<gblocks, 256>>>(hh, rowptr, adj, eps + i, cb, N);

        // GEMM1: z[N,256] = cb @ W1 -> bias, BN, ReLU (fp16 out)
        dim3 grid1(2, mblocks);
        gemm_mma_kernel<<<grid1, 256, dynSmem>>>(cb,
                                                 w1 + (size_t)i * 2 * DIM * DIM,
                                                 b1 + (size_t)i * 2 * DIM,
                                                 s1 + (size_t)i * 2 * DIM,
                                                 t1 + (size_t)i * 2 * DIM,
                                                 nullptr, zb,
                                                 N, DIM, 2 * DIM, 1, 0);

        dim3 grid2(1, mblocks);
        if (i < LNUM - 1) {
            // GEMM2: h[N,128] fp16 = z @ W2 -> bias, BN, ReLU
            gemm_mma_kernel<<<grid2, 256, dynSmem>>>(zb,
                                                     w2 + (size_t)i * 2 * DIM * DIM,
                                                     b2 + (size_t)i * DIM,
                                                     so + (size_t)i * DIM,
                                                     to + (size_t)i * DIM,
                                                     nullptr, hh,
                                                     N, 2 * DIM, DIM, 1, 0);
        } else {
            // final GEMM2 + fused log_softmax -> d_out fp32
            gemm_mma_kernel<<<grid2, 256, dynSmem>>>(zb,
                                                     w2 + (size_t)i * 2 * DIM * DIM,
                                                     b2 + (size_t)i * DIM,
                                                     nullptr, nullptr,
                                                     (float*)d_out, nullptr,
                                                     N, 2 * DIM, DIM, 0, 1);
        }
    }
}

// round 11
// speedup vs baseline: 5.5307x; 1.1046x over previous
#include <cuda_runtime.h>
#include <cuda_fp16.h>
#include <cstdint>
#include <math.h>

#define NMAX 50000
#define EMAX 800000
#define DIM  128
#define LNUM 3

// ---------------------------------------------------------------------------
// scratch (no allocation allowed)
// ---------------------------------------------------------------------------
__device__ __half g_hh [(size_t)NMAX * DIM];        // fp16 activations between layers (and x)
__device__ __half g_c  [(size_t)NMAX * DIM];        // GIN combine (GEMM1 input)
__device__ __half g_z  [(size_t)NMAX * 2 * DIM];    // z (GEMM2 input)
__device__ float g_s1[LNUM * 2 * DIM];
__device__ float g_t1[LNUM * 2 * DIM];
__device__ float g_so[(LNUM - 1) * DIM];
__device__ float g_to[(LNUM - 1) * DIM];
// transposed fp16 weights: W1T [L][256][128], W2T [L][128][256]
__device__ __half g_w1[LNUM * 2 * DIM * DIM];
__device__ __half g_w2[LNUM * 2 * DIM * DIM];
// CSR
__device__ int g_rowptr[NMAX + 1];
__device__ int g_cursor[NMAX];
__device__ int g_adj[EMAX];
__device__ int g_part[64];          // scan partials (<=49 blocks)

// ---------------------------------------------------------------------------
// helpers
// ---------------------------------------------------------------------------
__device__ __forceinline__ uint32_t smem_to_u32(const void* p) {
    uint32_t a;
    asm("{ .reg .u64 t; cvta.to.shared.u64 t, %1; cvt.u32.u64 %0, t; }" : "=r"(a) : "l"(p));
    return a;
}
__device__ __forceinline__ void ldmx4(uint32_t* r, uint32_t addr) {
    asm volatile("ldmatrix.sync.aligned.m8n8.x4.shared.b16 {%0,%1,%2,%3}, [%4];"
                 : "=r"(r[0]), "=r"(r[1]), "=r"(r[2]), "=r"(r[3]) : "r"(addr));
}
__device__ __forceinline__ void mma_f16(float* c, const uint32_t* a, uint32_t b0, uint32_t b1) {
    asm volatile("mma.sync.aligned.m16n8k16.row.col.f32.f16.f16.f32 "
                 "{%0,%1,%2,%3}, {%4,%5,%6,%7}, {%8,%9}, {%0,%1,%2,%3};"
                 : "+f"(c[0]), "+f"(c[1]), "+f"(c[2]), "+f"(c[3])
                 : "r"(a[0]), "r"(a[1]), "r"(a[2]), "r"(a[3]), "r"(b0), "r"(b1));
}
__device__ __forceinline__ void cp16(uint32_t saddr, const void* gptr) {
    asm volatile("cp.async.cg.shared.global [%0], [%1], 16;" :: "r"(saddr), "l"(gptr));
}
#define CP_COMMIT() asm volatile("cp.async.commit_group;" ::: "memory")
#define CP_WAIT1()  asm volatile("cp.async.wait_group 1;" ::: "memory")

// ---------------------------------------------------------------------------
// BN precompute
// ---------------------------------------------------------------------------
__global__ void bn_pre_kernel(const float* __restrict__ g1, const float* __restrict__ be1,
                              const float* __restrict__ m1, const float* __restrict__ v1,
                              const float* __restrict__ go, const float* __restrict__ bo,
                              const float* __restrict__ mo, const float* __restrict__ vo,
                              float* __restrict__ s1, float* __restrict__ t1,
                              float* __restrict__ so, float* __restrict__ to)
{
    int t = blockIdx.x * blockDim.x + threadIdx.x;
    if (t < LNUM * 2 * DIM) {
        float sc = g1[t] * rsqrtf(v1[t] + 1e-5f);
        s1[t] = sc;
        t1[t] = be1[t] - m1[t] * sc;
    }
    if (t < (LNUM - 1) * DIM) {
        float sc = go[t] * rsqrtf(vo[t] + 1e-5f);
        so[t] = sc;
        to[t] = bo[t] - mo[t] * sc;
    }
}

// ---------------------------------------------------------------------------
// x -> fp16 pre-convert
// ---------------------------------------------------------------------------
__global__ void xconv_kernel(const float* __restrict__ x, __half* __restrict__ xh, int n)
{
    int i = blockIdx.x * blockDim.x + threadIdx.x;
    if (i < n) {
        float2 v = *((const float2*)x + i);
        __half2 p = __floats2half2_rn(v.x, v.y);
        *((__half2*)xh + i) = p;
    }
}

// ---------------------------------------------------------------------------
// Weight transpose + fp16 round.
// ---------------------------------------------------------------------------
__global__ void wconv_kernel(const float* __restrict__ W1, const float* __restrict__ W2,
                             __half* __restrict__ w1, __half* __restrict__ w2)
{
    int idx = blockIdx.x * blockDim.x + threadIdx.x;
    const int tot = LNUM * 2 * DIM * DIM;
    if (idx >= tot) return;
    int l = idx / (2 * DIM * DIM);
    int rem = idx % (2 * DIM * DIM);
    {
        int n = rem / DIM, k = rem % DIM;
        w1[idx] = __float2half_rn(W1[(size_t)l * DIM * 2 * DIM + (size_t)k * 2 * DIM + n]);
    }
    {
        int n2 = rem / (2 * DIM), k2 = rem % (2 * DIM);
        w2[idx] = __float2half_rn(W2[(size_t)l * 2 * DIM * DIM + (size_t)k2 * DIM + n2]);
    }
}

// ---------------------------------------------------------------------------
// CSR build: zero -> hist -> 2-level parallel scan -> fill
// ---------------------------------------------------------------------------
__global__ void zero_cnt_kernel(int* __restrict__ cnt, int n)
{
    int i = blockIdx.x * blockDim.x + threadIdx.x;
    if (i < n) cnt[i] = 0;
}
__global__ void hist_kernel(const int* __restrict__ dst, int* __restrict__ cnt, int E)
{
    int e = blockIdx.x * blockDim.x + threadIdx.x;
    if (e < E) atomicAdd(&cnt[dst[e] + 1], 1);
}
// level-1: per-block inclusive scan over 1024 elems; write block total
__global__ void scan1_kernel(int* __restrict__ cnt, int* __restrict__ part, int n)
{
    __shared__ int wsum[32];
    int tid = threadIdx.x, lane = tid & 31, wid = tid >> 5;
    int i = blockIdx.x * 1024 + tid;
    int v = (i < n) ? cnt[i] : 0;
    int s = v;
#pragma unroll
    for (int o = 1; o < 32; o <<= 1) {
        int t = __shfl_up_sync(0xffffffffu, s, o);
        if (lane >= o) s += t;
    }
    if (lane == 31) wsum[wid] = s;
    __syncthreads();
    if (wid == 0) {
        int w = wsum[lane];
#pragma unroll
        for (int o = 1; o < 32; o <<= 1) {
            int t = __shfl_up_sync(0xffffffffu, w, o);
            if (lane >= o) w += t;
        }
        wsum[lane] = w;
    }
    __syncthreads();
    int inc = s + (wid ? wsum[wid - 1] : 0);
    if (i < n) cnt[i] = inc;
    if (tid == 1023) part[blockIdx.x] = inc;
}
// level-2: scan partials (<=64) with 2 warps — FIXED: use LOCAL lane for shfl
// guard and an explicit cross-warp carry.
__global__ void scan2_kernel(int* __restrict__ part, int nb)
{
    int tid = threadIdx.x;            // 0..63
    int lane = tid & 31;              // local lane
    int wid = tid >> 5;
    int v = (tid < nb) ? part[tid] : 0;
    int s = v;
#pragma unroll
    for (int o = 1; o < 32; o <<= 1) {
        int t = __shfl_up_sync(0xffffffffu, s, o);
        if (lane >= o) s += t;
    }
    __shared__ int w0tot;
    if (tid == 31) w0tot = s;
    __syncthreads();
    if (wid == 1) s += w0tot;
    if (tid < nb) part[tid] = s;
}
// level-3: add carry + write cursor
__global__ void scan3_kernel(int* __restrict__ cnt, const int* __restrict__ part,
                             int* __restrict__ cur, int n)
{
    int i = blockIdx.x * 1024 + threadIdx.x;
    if (i >= n) return;
    int v = cnt[i];
    if (blockIdx.x > 0) v += part[blockIdx.x - 1];
    cnt[i] = v;
    if (i < n - 1) cur[i] = v;
}
__global__ void fill_kernel(const int* __restrict__ src, const int* __restrict__ dst,
                            int* __restrict__ cur, int* __restrict__ adj, int E)
{
    int e = blockIdx.x * blockDim.x + threadIdx.x;
    if (e < E) {
        int pos = atomicAdd(&cur[dst[e]], 1);
        adj[pos] = src[e];
    }
}

// ---------------------------------------------------------------------------
// Gather (fp16 h) + GIN combine -> single fp16 buffer.  ILP-4.
// one warp per node, lane covers 4 dims (uint2 = 4 halves)
// ---------------------------------------------------------------------------
__global__ __launch_bounds__(256)
void gather_kernel(const __half* __restrict__ h, const int* __restrict__ rowptr,
                   const int* __restrict__ adj, const float* __restrict__ epsp,
                   __half* __restrict__ cbuf, int N)
{
    int node = blockIdx.x * 8 + (threadIdx.x >> 5);
    int lane = threadIdx.x & 31;
    if (node >= N) return;

    int beg = rowptr[node], end = rowptr[node + 1];
    float4 s0 = make_float4(0.f, 0.f, 0.f, 0.f);
    float4 s1 = make_float4(0.f, 0.f, 0.f, 0.f);
    float4 s2 = make_float4(0.f, 0.f, 0.f, 0.f);
    float4 s3 = make_float4(0.f, 0.f, 0.f, 0.f);

    for (int e = beg; e < end; e += 32) {
        int a = (e + lane < end) ? __ldg(adj + e + lane) : -1;
        int cnt = min(32, end - e);
        int j = 0;
        for (; j + 3 < cnt; j += 4) {
            int n0 = __shfl_sync(0xffffffffu, a, j);
            int n1 = __shfl_sync(0xffffffffu, a, j + 1);
            int n2 = __shfl_sync(0xffffffffu, a, j + 2);
            int n3 = __shfl_sync(0xffffffffu, a, j + 3);
            uint2 r0 = __ldg((const uint2*)(h + (size_t)n0 * DIM) + lane);
            uint2 r1 = __ldg((const uint2*)(h + (size_t)n1 * DIM) + lane);
            uint2 r2 = __ldg((const uint2*)(h + (size_t)n2 * DIM) + lane);
            uint2 r3 = __ldg((const uint2*)(h + (size_t)n3 * DIM) + lane);
            float2 p;
            p = __half22float2(*(__half2*)&r0.x); s0.x += p.x; s0.y += p.y;
            p = __half22float2(*(__half2*)&r0.y); s0.z += p.x; s0.w += p.y;
            p = __half22float2(*(__half2*)&r1.x); s1.x += p.x; s1.y += p.y;
            p = __half22float2(*(__half2*)&r1.y); s1.z += p.x; s1.w += p.y;
            p = __half22float2(*(__half2*)&r2.x); s2.x += p.x; s2.y += p.y;
            p = __half22float2(*(__half2*)&r2.y); s2.z += p.x; s2.w += p.y;
            p = __half22float2(*(__half2*)&r3.x); s3.x += p.x; s3.y += p.y;
            p = __half22float2(*(__half2*)&r3.y); s3.z += p.x; s3.w += p.y;
        }
        for (; j < cnt; j++) {
            int n0 = __shfl_sync(0xffffffffu, a, j);
            uint2 r0 = __ldg((const uint2*)(h + (size_t)n0 * DIM) + lane);
            float2 p;
            p = __half22float2(*(__half2*)&r0.x); s0.x += p.x; s0.y += p.y;
            p = __half22float2(*(__half2*)&r0.y); s0.z += p.x; s0.w += p.y;
        }
    }

    float epsv = 1.0f + epsp[0];
    uint2 hraw = __ldg((const uint2*)(h + (size_t)node * DIM) + lane);
    float2 h01 = __half22float2(*(__half2*)&hraw.x);
    float2 h23 = __half22float2(*(__half2*)&hraw.y);
    __half2 c01 = __floats2half2_rn(fmaf(epsv, h01.x, (s0.x + s1.x) + (s2.x + s3.x)),
                                    fmaf(epsv, h01.y, (s0.y + s1.y) + (s2.y + s3.y)));
    __half2 c23 = __floats2half2_rn(fmaf(epsv, h23.x, (s0.z + s1.z) + (s2.z + s3.z)),
                                    fmaf(epsv, h23.y, (s0.w + s1.w) + (s2.w + s3.w)));
    uint2 outp = make_uint2(*(uint32_t*)&c01, *(uint32_t*)&c23);
    *((uint2*)(cbuf + (size_t)node * DIM) + lane) = outp;
}

// ---------------------------------------------------------------------------
// FP16 mma.sync GEMM, cp.async 3-stage pipeline.
//   block 128x128, 8 warps (2M x 4N), warp tile 64x32, BK=32.
//   Every loop iteration commits EXACTLY one group (empty when past the end),
//   so wait_group 1 at iteration c guarantees chunk c's group is complete.
//   Output: fp32 (Cf, + dosm=fused log_softmax when grid.x==1) or fp16 (Ch).
// ---------------------------------------------------------------------------
#define BK 32
#define ASTRIDE 40                 // fp16 per smem row (80 B, conflict-free)
#define ABUF_B (128 * ASTRIDE * 2) // 10240 B per buffer
#define STAGE_B (2 * ABUF_B)       // A, W
#define NSTAGE 3

__global__ __launch_bounds__(256)
void gemm_mma_kernel(const __half* __restrict__ A, const __half* __restrict__ W,
                     const float* __restrict__ bias, const float* __restrict__ bns,
                     const float* __restrict__ bnt,
                     float* __restrict__ Cf, __half* __restrict__ Ch,
                     int M, int K, int Nc, int relu, int dosm)
{
    extern __shared__ char smem[];
    __shared__ float smax[128][4];
    __shared__ float ssum[128][4];
    const int tid = threadIdx.x;
    const int lane = tid & 31, wid = tid >> 5;
    const int warpM = wid >> 2, warpN = wid & 3;
    const int rowBase = blockIdx.y * 128;
    const int colBase = blockIdx.x * 128;
    const uint32_t sbase = smem_to_u32(smem);

    // per-thread cp.async mapping: 4 ops of 16B (2 for A tile, 2 for W tile)
    // idx = tid + i*256 in 0..511: row = idx>>2 (0..127), q = idx&3 (16B slot)
    const __half* asrc[2];
    const __half* wsrc[2];
    uint32_t adst[2], wdst[2];
#pragma unroll
    for (int i = 0; i < 2; i++) {
        int idx = tid + i * 256;
        int row = idx >> 2, q = idx & 3;
        int g = rowBase + row;
        if (g >= M) g = M - 1;            // clamp (garbage rows unused)
        asrc[i] = A + (size_t)g * K + q * 8;
        wsrc[i] = W + (size_t)(colBase + row) * K + q * 8;
        adst[i] = row * (ASTRIDE * 2) + q * 16;
        wdst[i] = ABUF_B + row * (ASTRIDE * 2) + q * 16;
    }

    float acc[4][4][4];
#pragma unroll
    for (int a = 0; a < 4; a++)
#pragma unroll
        for (int b = 0; b < 4; b++)
#pragma unroll
            for (int c = 0; c < 4; c++) acc[a][b][c] = 0.f;

    const int frow = lane & 15, fk = (lane >> 4) * 8;
    uint32_t offA[4], offB[2];
#pragma unroll
    for (int mf = 0; mf < 4; mf++)
        offA[mf] = ((warpM * 64 + mf * 16 + frow) * ASTRIDE + fk) * 2;
#pragma unroll
    for (int nb = 0; nb < 2; nb++)
        offB[nb] = ((warpN * 32 + nb * 16 + frow) * ASTRIDE + fk) * 2;

    const int nch = K / BK;

    // ---- prologue: issue stages 0,1 (groups 0,1) ----
#pragma unroll
    for (int pc = 0; pc < 2; pc++) {
        uint32_t sb = sbase + pc * STAGE_B;
        int koff = pc * BK;
#pragma unroll
        for (int i = 0; i < 2; i++) {
            cp16(sb + adst[i], asrc[i] + koff);
            cp16(sb + wdst[i], wsrc[i] + koff);
        }
        CP_COMMIT();
    }

    for (int c = 0; c < nch; c++) {
        // groups committed so far = c + 2; wait ≤1 pending => group c complete
        CP_WAIT1();
        __syncthreads();

        if (c + 2 < nch) {
            uint32_t sb = sbase + ((c + 2) % NSTAGE) * STAGE_B;
            int koff = (c + 2) * BK;
#pragma unroll
            for (int i = 0; i < 2; i++) {
                cp16(sb + adst[i], asrc[i] + koff);
                cp16(sb + wdst[i], wsrc[i] + koff);
            }
            CP_COMMIT();
        } else {
            CP_COMMIT();   // empty group keeps the wait accounting uniform
        }

        uint32_t bufA = sbase + (c % NSTAGE) * STAGE_B;
        uint32_t bufW = bufA + ABUF_B;
#pragma unroll
        for (int ks = 0; ks < 2; ks++) {
            uint32_t ar[4][4], bw[2][4];
#pragma unroll
            for (int mf = 0; mf < 4; mf++)
                ldmx4(ar[mf], bufA + offA[mf] + ks * 32);
#pragma unroll
            for (int nb = 0; nb < 2; nb++)
                ldmx4(bw[nb], bufW + offB[nb] + ks * 32);
#pragma unroll
            for (int mf = 0; mf < 4; mf++) {
#pragma unroll
                for (int nf = 0; nf < 4; nf++) {
                    int nb = nf >> 1, sel = nf & 1;
                    mma_f16(acc[mf][nf], ar[mf], bw[nb][sel], bw[nb][sel + 2]);
                }
            }
        }
        __syncthreads();   // protect stage (c % NSTAGE) from being overwritten
    }

    // ---- epilogue ----
    const int g = lane >> 2, tig = lane & 3;
    float bj0[4], bj1[4], sj0[4], sj1[4], tj0[4], tj1[4];
#pragma unroll
    for (int nf = 0; nf < 4; nf++) {
        int col = colBase + warpN * 32 + nf * 8 + 2 * tig;
        bj0[nf] = bias[col];
        bj1[nf] = bias[col + 1];
        if (bns) {
            sj0[nf] = bns[col];  sj1[nf] = bns[col + 1];
            tj0[nf] = bnt[col];  tj1[nf] = bnt[col + 1];
        }
    }
#pragma unroll
    for (int mf = 0; mf < 4; mf++)
#pragma unroll
        for (int nf = 0; nf < 4; nf++)
#pragma unroll
            for (int half = 0; half < 2; half++) {
                float v0 = acc[mf][nf][half * 2 + 0] + bj0[nf];
                float v1 = acc[mf][nf][half * 2 + 1] + bj1[nf];
                if (bns) {
                    v0 = fmaf(v0, sj0[nf], tj0[nf]);
                    v1 = fmaf(v1, sj1[nf], tj1[nf]);
                }
                if (relu) { v0 = fmaxf(v0, 0.f); v1 = fmaxf(v1, 0.f); }
                acc[mf][nf][half * 2 + 0] = v0;
                acc[mf][nf][half * 2 + 1] = v1;
            }

    if (dosm) {
        float rowmax[4][2];
#pragma unroll
        for (int mf = 0; mf < 4; mf++)
#pragma unroll
            for (int half = 0; half < 2; half++) {
                float mx = -1e30f;
#pragma unroll
                for (int nf = 0; nf < 4; nf++) {
                    mx = fmaxf(mx, acc[mf][nf][half * 2 + 0]);
                    mx = fmaxf(mx, acc[mf][nf][half * 2 + 1]);
                }
                mx = fmaxf(mx, __shfl_xor_sync(0xffffffffu, mx, 1));
                mx = fmaxf(mx, __shfl_xor_sync(0xffffffffu, mx, 2));
                int row = warpM * 64 + mf * 16 + g + half * 8;
                if (tig == 0) smax[row][warpN] = mx;
            }
        __syncthreads();
#pragma unroll
        for (int mf = 0; mf < 4; mf++)
#pragma unroll
            for (int half = 0; half < 2; half++) {
                int row = warpM * 64 + mf * 16 + g + half * 8;
                float mx = fmaxf(fmaxf(smax[row][0], smax[row][1]),
                                 fmaxf(smax[row][2], smax[row][3]));
                rowmax[mf][half] = mx;
                float se = 0.f;
#pragma unroll
                for (int nf = 0; nf < 4; nf++) {
                    se += expf(acc[mf][nf][half * 2 + 0] - mx);
                    se += expf(acc[mf][nf][half * 2 + 1] - mx);
                }
                se += __shfl_xor_sync(0xffffffffu, se, 1);
                se += __shfl_xor_sync(0xffffffffu, se, 2);
                if (tig == 0) ssum[row][warpN] = se;
            }
        __syncthreads();
#pragma unroll
        for (int mf = 0; mf < 4; mf++)
#pragma unroll
            for (int half = 0; half < 2; half++) {
                int row = warpM * 64 + mf * 16 + g + half * 8;
                int grow = rowBase + row;
                if (grow >= M) continue;
                float tot = ssum[row][0] + ssum[row][1] + ssum[row][2] + ssum[row][3];
                float lse = rowmax[mf][half] + logf(tot);
#pragma unroll
                for (int nf = 0; nf < 4; nf++) {
                    int col = colBase + warpN * 32 + nf * 8 + 2 * tig;
                    float2 o = make_float2(acc[mf][nf][half * 2 + 0] - lse,
                                           acc[mf][nf][half * 2 + 1] - lse);
                    *(float2*)(Cf + (size_t)grow * Nc + col) = o;
                }
            }
        return;
    }

#pragma unroll
    for (int mf = 0; mf < 4; mf++)
#pragma unroll
        for (int half = 0; half < 2; half++) {
            int row = rowBase + warpM * 64 + mf * 16 + g + half * 8;
            if (row >= M) continue;
#pragma unroll
            for (int nf = 0; nf < 4; nf++) {
                int col = colBase + warpN * 32 + nf * 8 + 2 * tig;
                float v0 = acc[mf][nf][half * 2 + 0];
                float v1 = acc[mf][nf][half * 2 + 1];
                if (Cf) {
                    *(float2*)(Cf + (size_t)row * Nc + col) = make_float2(v0, v1);
                } else {
                    __half2 p = __floats2half2_rn(v0, v1);
                    *(uint32_t*)(Ch + (size_t)row * Nc + col) = *(uint32_t*)&p;
                }
            }
        }
}

// ---------------------------------------------------------------------------
extern "C" void kernel_launch(void* const* d_in, const int* in_sizes, int n_in,
                              void* d_out, int out_size)
{
    const float* x    = (const float*)d_in[0];
    const int*   ei   = (const int*)  d_in[1];
    const float* W1   = (const float*)d_in[2];
    const float* b1   = (const float*)d_in[3];
    const float* g1   = (const float*)d_in[4];
    const float* be1  = (const float*)d_in[5];
    const float* m1   = (const float*)d_in[6];
    const float* v1   = (const float*)d_in[7];
    const float* W2   = (const float*)d_in[8];
    const float* b2   = (const float*)d_in[9];
    const float* eps  = (const float*)d_in[10];
    const float* go   = (const float*)d_in[11];
    const float* bo   = (const float*)d_in[12];
    const float* mo   = (const float*)d_in[13];
    const float* vo   = (const float*)d_in[14];

    int N = in_sizes[0] / DIM;
    int E = in_sizes[1] / 2;

    float *s1, *t1, *so, *to;
    __half *hh, *cb, *zb, *w1, *w2;
    int *rowptr, *cursor, *adj, *part;
    cudaGetSymbolAddress((void**)&hh,     g_hh);
    cudaGetSymbolAddress((void**)&cb,     g_c);
    cudaGetSymbolAddress((void**)&zb,     g_z);
    cudaGetSymbolAddress((void**)&s1,     g_s1);
    cudaGetSymbolAddress((void**)&t1,     g_t1);
    cudaGetSymbolAddress((void**)&so,     g_so);
    cudaGetSymbolAddress((void**)&to,     g_to);
    cudaGetSymbolAddress((void**)&w1,     g_w1);
    cudaGetSymbolAddress((void**)&w2,     g_w2);
    cudaGetSymbolAddress((void**)&rowptr, g_rowptr);
    cudaGetSymbolAddress((void**)&cursor, g_cursor);
    cudaGetSymbolAddress((void**)&adj,    g_adj);
    cudaGetSymbolAddress((void**)&part,   g_part);

    const int dynSmem = NSTAGE * STAGE_B;  // 61440 B
    cudaFuncSetAttribute(gemm_mma_kernel, cudaFuncAttributeMaxDynamicSharedMemorySize, dynSmem);

    const int* src = ei;
    const int* dst = ei + E;

    // ---- setup: BN folding, x/weight conversion, CSR build ----
    bn_pre_kernel<<<1, LNUM * 2 * DIM>>>(g1, be1, m1, v1, go, bo, mo, vo, s1, t1, so, to);
    xconv_kernel<<<(N * DIM / 2 + 255) / 256, 256>>>(x, hh, N * DIM / 2);
    {
        int tot = LNUM * 2 * DIM * DIM;
        wconv_kernel<<<(tot + 255) / 256, 256>>>(W1, W2, w1, w2);
    }
    int n1 = N + 1;
    int sblocks = (n1 + 1023) / 1024;
    zero_cnt_kernel<<<(n1 + 255) / 256, 256>>>(rowptr, n1);
    hist_kernel<<<(E + 255) / 256, 256>>>(dst, rowptr, E);
    scan1_kernel<<<sblocks, 1024>>>(rowptr, part, n1);
    scan2_kernel<<<1, 64>>>(part, sblocks);
    scan3_kernel<<<sblocks, 1024>>>(rowptr, part, cursor, n1);
    fill_kernel<<<(E + 255) / 256, 256>>>(src, dst, cursor, adj, E);

    int mblocks = (N + 127) / 128;
    int gblocks = (N + 7) / 8;

    for (int i = 0; i < LNUM; i++) {
        gather_kernel<<<gblocks, 256>>>(hh, rowptr, adj, eps + i, cb, N);

        dim3 grid1(2, mblocks);
        gemm_mma_kernel<<<grid1, 256, dynSmem>>>(cb,
                                                 w1 + (size_t)i * 2 * DIM * DIM,
                                                 b1 + (size_t)i * 2 * DIM,
                                                 s1 + (size_t)i * 2 * DIM,
                                                 t1 + (size_t)i * 2 * DIM,
                                                 nullptr, zb,
                                                 N, DIM, 2 * DIM, 1, 0);

        dim3 grid2(1, mblocks);
        if (i < LNUM - 1) {
            gemm_mma_kernel<<<grid2, 256, dynSmem>>>(zb,
                                                     w2 + (size_t)i * 2 * DIM * DIM,
                                                     b2 + (size_t)i * DIM,
                                                     so + (size_t)i * DIM,
                                                     to + (size_t)i * DIM,
                                                     nullptr, hh,
                                                     N, 2 * DIM, DIM, 1, 0);
        } else {
            gemm_mma_kernel<<<grid2, 256, dynSmem>>>(zb,
                                                     w2 + (size_t)i * 2 * DIM * DIM,
                                                     b2 + (size_t)i * DIM,
                                                     nullptr, nullptr,
                                                     (float*)d_out, nullptr,
                                                     N, 2 * DIM, DIM, 0, 1);
        }
    }
}

// round 13
// speedup vs baseline: 5.6205x; 1.0162x over previous
#include <cuda_runtime.h>
#include <cuda_fp16.h>
#include <cstdint>
#include <math.h>

#define NMAX 50000
#define EMAX 800000
#define DIM  128
#define LNUM 3

// ---------------------------------------------------------------------------
// scratch (no allocation allowed)
// ---------------------------------------------------------------------------
__device__ __half g_hh [(size_t)NMAX * DIM];        // fp16 activations between layers (and x)
__device__ __half g_c  [(size_t)NMAX * DIM];        // GIN combine (GEMM1 input)
__device__ __half g_z  [(size_t)NMAX * 2 * DIM];    // z (GEMM2 input)
__device__ float g_s1[LNUM * 2 * DIM];
__device__ float g_t1[LNUM * 2 * DIM];
__device__ float g_so[(LNUM - 1) * DIM];
__device__ float g_to[(LNUM - 1) * DIM];
// transposed fp16 weights: W1T [L][256][128], W2T [L][128][256]
__device__ __half g_w1[LNUM * 2 * DIM * DIM];
__device__ __half g_w2[LNUM * 2 * DIM * DIM];
// CSR
__device__ int g_rowptr[NMAX + 1];
__device__ int g_cursor[NMAX];
__device__ int g_adj[EMAX];
__device__ int g_part[64];          // scan partials (<=49 blocks)

// ---------------------------------------------------------------------------
// helpers
// ---------------------------------------------------------------------------
__device__ __forceinline__ uint32_t smem_to_u32(const void* p) {
    uint32_t a;
    asm("{ .reg .u64 t; cvta.to.shared.u64 t, %1; cvt.u32.u64 %0, t; }" : "=r"(a) : "l"(p));
    return a;
}
__device__ __forceinline__ void ldmx4(uint32_t* r, uint32_t addr) {
    asm volatile("ldmatrix.sync.aligned.m8n8.x4.shared.b16 {%0,%1,%2,%3}, [%4];"
                 : "=r"(r[0]), "=r"(r[1]), "=r"(r[2]), "=r"(r[3]) : "r"(addr));
}
__device__ __forceinline__ void mma_f16(float* c, const uint32_t* a, uint32_t b0, uint32_t b1) {
    asm volatile("mma.sync.aligned.m16n8k16.row.col.f32.f16.f16.f32 "
                 "{%0,%1,%2,%3}, {%4,%5,%6,%7}, {%8,%9}, {%0,%1,%2,%3};"
                 : "+f"(c[0]), "+f"(c[1]), "+f"(c[2]), "+f"(c[3])
                 : "r"(a[0]), "r"(a[1]), "r"(a[2]), "r"(a[3]), "r"(b0), "r"(b1));
}
__device__ __forceinline__ void cp16(uint32_t saddr, const void* gptr) {
    asm volatile("cp.async.cg.shared.global [%0], [%1], 16;" :: "r"(saddr), "l"(gptr));
}
#define CP_COMMIT() asm volatile("cp.async.commit_group;" ::: "memory")
#define CP_WAIT1()  asm volatile("cp.async.wait_group 1;" ::: "memory")

// ---------------------------------------------------------------------------
// Fused setup: BN fold + x->fp16 + weight transpose/round.  One launch.
// ---------------------------------------------------------------------------
__global__ void setup_kernel(const float* __restrict__ x, __half* __restrict__ xh, int nx2,
                             const float* __restrict__ W1, const float* __restrict__ W2,
                             __half* __restrict__ w1, __half* __restrict__ w2, int wtot,
                             const float* __restrict__ g1, const float* __restrict__ be1,
                             const float* __restrict__ m1, const float* __restrict__ v1,
                             const float* __restrict__ go, const float* __restrict__ bo,
                             const float* __restrict__ mo, const float* __restrict__ vo,
                             float* __restrict__ s1, float* __restrict__ t1,
                             float* __restrict__ so, float* __restrict__ to)
{
    int i = blockIdx.x * blockDim.x + threadIdx.x;
    if (i < nx2) {
        float2 v = *((const float2*)x + i);
        __half2 p = __floats2half2_rn(v.x, v.y);
        *((__half2*)xh + i) = p;
    }
    if (i < wtot) {
        int l = i / (2 * DIM * DIM);
        int rem = i % (2 * DIM * DIM);
        {
            int n = rem / DIM, k = rem % DIM;
            w1[i] = __float2half_rn(W1[(size_t)l * DIM * 2 * DIM + (size_t)k * 2 * DIM + n]);
        }
        {
            int n2 = rem / (2 * DIM), k2 = rem % (2 * DIM);
            w2[i] = __float2half_rn(W2[(size_t)l * 2 * DIM * DIM + (size_t)k2 * DIM + n2]);
        }
    }
    if (i < LNUM * 2 * DIM) {
        float sc = g1[i] * rsqrtf(v1[i] + 1e-5f);
        s1[i] = sc;
        t1[i] = be1[i] - m1[i] * sc;
    }
    if (i < (LNUM - 1) * DIM) {
        float sc = go[i] * rsqrtf(vo[i] + 1e-5f);
        so[i] = sc;
        to[i] = bo[i] - mo[i] * sc;
    }
}

// ---------------------------------------------------------------------------
// CSR build: memset -> hist -> 2-level parallel scan -> fill
// ---------------------------------------------------------------------------
__global__ void hist_kernel(const int* __restrict__ dst, int* __restrict__ cnt, int E)
{
    int e = blockIdx.x * blockDim.x + threadIdx.x;
    if (e < E) atomicAdd(&cnt[dst[e] + 1], 1);
}
// level-1: per-block inclusive scan over 1024 elems; write block total
__global__ void scan1_kernel(int* __restrict__ cnt, int* __restrict__ part, int n)
{
    __shared__ int wsum[32];
    int tid = threadIdx.x, lane = tid & 31, wid = tid >> 5;
    int i = blockIdx.x * 1024 + tid;
    int v = (i < n) ? cnt[i] : 0;
    int s = v;
#pragma unroll
    for (int o = 1; o < 32; o <<= 1) {
        int t = __shfl_up_sync(0xffffffffu, s, o);
        if (lane >= o) s += t;
    }
    if (lane == 31) wsum[wid] = s;
    __syncthreads();
    if (wid == 0) {
        int w = wsum[lane];
#pragma unroll
        for (int o = 1; o < 32; o <<= 1) {
            int t = __shfl_up_sync(0xffffffffu, w, o);
            if (lane >= o) w += t;
        }
        wsum[lane] = w;
    }
    __syncthreads();
    int inc = s + (wid ? wsum[wid - 1] : 0);
    if (i < n) cnt[i] = inc;
    if (tid == 1023) part[blockIdx.x] = inc;
}
// level-2: scan partials (<=64) with 2 warps, LOCAL lane guard + explicit carry
__global__ void scan2_kernel(int* __restrict__ part, int nb)
{
    int tid = threadIdx.x;            // 0..63
    int lane = tid & 31;
    int wid = tid >> 5;
    int v = (tid < nb) ? part[tid] : 0;
    int s = v;
#pragma unroll
    for (int o = 1; o < 32; o <<= 1) {
        int t = __shfl_up_sync(0xffffffffu, s, o);
        if (lane >= o) s += t;
    }
    __shared__ int w0tot;
    if (tid == 31) w0tot = s;
    __syncthreads();
    if (wid == 1) s += w0tot;
    if (tid < nb) part[tid] = s;
}
// level-3: add carry + write cursor
__global__ void scan3_kernel(int* __restrict__ cnt, const int* __restrict__ part,
                             int* __restrict__ cur, int n)
{
    int i = blockIdx.x * 1024 + threadIdx.x;
    if (i >= n) return;
    int v = cnt[i];
    if (blockIdx.x > 0) v += part[blockIdx.x - 1];
    cnt[i] = v;
    if (i < n - 1) cur[i] = v;
}
__global__ void fill_kernel(const int* __restrict__ src, const int* __restrict__ dst,
                            int* __restrict__ cur, int* __restrict__ adj, int E)
{
    int e = blockIdx.x * blockDim.x + threadIdx.x;
    if (e < E) {
        int pos = atomicAdd(&cur[dst[e]], 1);
        adj[pos] = src[e];
    }
}

// ---------------------------------------------------------------------------
// Gather (fp16 h) + GIN combine -> single fp16 buffer.  ILP-4.
// one warp per node, lane covers 4 dims (uint2 = 4 halves)
// ---------------------------------------------------------------------------
__global__ __launch_bounds__(256)
void gather_kernel(const __half* __restrict__ h, const int* __restrict__ rowptr,
                   const int* __restrict__ adj, const float* __restrict__ epsp,
                   __half* __restrict__ cbuf, int N)
{
    int node = blockIdx.x * 8 + (threadIdx.x >> 5);
    int lane = threadIdx.x & 31;
    if (node >= N) return;

    int beg = rowptr[node], end = rowptr[node + 1];
    float4 s0 = make_float4(0.f, 0.f, 0.f, 0.f);
    float4 s1 = make_float4(0.f, 0.f, 0.f, 0.f);
    float4 s2 = make_float4(0.f, 0.f, 0.f, 0.f);
    float4 s3 = make_float4(0.f, 0.f, 0.f, 0.f);

    for (int e = beg; e < end; e += 32) {
        int a = (e + lane < end) ? __ldg(adj + e + lane) : -1;
        int cnt = min(32, end - e);
        int j = 0;
        for (; j + 3 < cnt; j += 4) {
            int n0 = __shfl_sync(0xffffffffu, a, j);
            int n1 = __shfl_sync(0xffffffffu, a, j + 1);
            int n2 = __shfl_sync(0xffffffffu, a, j + 2);
            int n3 = __shfl_sync(0xffffffffu, a, j + 3);
            uint2 r0 = __ldg((const uint2*)(h + (size_t)n0 * DIM) + lane);
            uint2 r1 = __ldg((const uint2*)(h + (size_t)n1 * DIM) + lane);
            uint2 r2 = __ldg((const uint2*)(h + (size_t)n2 * DIM) + lane);
            uint2 r3 = __ldg((const uint2*)(h + (size_t)n3 * DIM) + lane);
            float2 p;
            p = __half22float2(*(__half2*)&r0.x); s0.x += p.x; s0.y += p.y;
            p = __half22float2(*(__half2*)&r0.y); s0.z += p.x; s0.w += p.y;
            p = __half22float2(*(__half2*)&r1.x); s1.x += p.x; s1.y += p.y;
            p = __half22float2(*(__half2*)&r1.y); s1.z += p.x; s1.w += p.y;
            p = __half22float2(*(__half2*)&r2.x); s2.x += p.x; s2.y += p.y;
            p = __half22float2(*(__half2*)&r2.y); s2.z += p.x; s2.w += p.y;
            p = __half22float2(*(__half2*)&r3.x); s3.x += p.x; s3.y += p.y;
            p = __half22float2(*(__half2*)&r3.y); s3.z += p.x; s3.w += p.y;
        }
        for (; j < cnt; j++) {
            int n0 = __shfl_sync(0xffffffffu, a, j);
            uint2 r0 = __ldg((const uint2*)(h + (size_t)n0 * DIM) + lane);
            float2 p;
            p = __half22float2(*(__half2*)&r0.x); s0.x += p.x; s0.y += p.y;
            p = __half22float2(*(__half2*)&r0.y); s0.z += p.x; s0.w += p.y;
        }
    }

    float epsv = 1.0f + epsp[0];
    uint2 hraw = __ldg((const uint2*)(h + (size_t)node * DIM) + lane);
    float2 h01 = __half22float2(*(__half2*)&hraw.x);
    float2 h23 = __half22float2(*(__half2*)&hraw.y);
    __half2 c01 = __floats2half2_rn(fmaf(epsv, h01.x, (s0.x + s1.x) + (s2.x + s3.x)),
                                    fmaf(epsv, h01.y, (s0.y + s1.y) + (s2.y + s3.y)));
    __half2 c23 = __floats2half2_rn(fmaf(epsv, h23.x, (s0.z + s1.z) + (s2.z + s3.z)),
                                    fmaf(epsv, h23.y, (s0.w + s1.w) + (s2.w + s3.w)));
    uint2 outp = make_uint2(*(uint32_t*)&c01, *(uint32_t*)&c23);
    *((uint2*)(cbuf + (size_t)node * DIM) + lane) = outp;
}

// ---------------------------------------------------------------------------
// FP16 mma.sync GEMM, cp.async 3-stage pipeline, ONE barrier per chunk.
//   Safety: at iteration c the write target (c+2)%3 == (c-1)%3, whose last
//   readers all passed the iteration-c leading __syncthreads.
//   Output: fp32 (Cf, + dosm=fused log_softmax when grid.x==1) or fp16 (Ch).
// ---------------------------------------------------------------------------
#define BK 32
#define ASTRIDE 40                 // fp16 per smem row (80 B, conflict-free)
#define ABUF_B (128 * ASTRIDE * 2) // 10240 B per buffer
#define STAGE_B (2 * ABUF_B)       // A, W
#define NSTAGE 3

__global__ __launch_bounds__(256)
void gemm_mma_kernel(const __half* __restrict__ A, const __half* __restrict__ W,
                     const float* __restrict__ bias, const float* __restrict__ bns,
                     const float* __restrict__ bnt,
                     float* __restrict__ Cf, __half* __restrict__ Ch,
                     int M, int K, int Nc, int relu, int dosm)
{
    extern __shared__ char smem[];
    __shared__ float smax[128][4];
    __shared__ float ssum[128][4];
    const int tid = threadIdx.x;
    const int lane = tid & 31, wid = tid >> 5;
    const int warpM = wid >> 2, warpN = wid & 3;
    const int rowBase = blockIdx.y * 128;
    const int colBase = blockIdx.x * 128;
    const uint32_t sbase = smem_to_u32(smem);

    // per-thread cp.async mapping: 4 ops of 16B (2 for A tile, 2 for W tile)
    const __half* asrc[2];
    const __half* wsrc[2];
    uint32_t adst[2], wdst[2];
#pragma unroll
    for (int i = 0; i < 2; i++) {
        int idx = tid + i * 256;
        int row = idx >> 2, q = idx & 3;
        int g = rowBase + row;
        if (g >= M) g = M - 1;            // clamp (garbage rows unused)
        asrc[i] = A + (size_t)g * K + q * 8;
        wsrc[i] = W + (size_t)(colBase + row) * K + q * 8;
        adst[i] = row * (ASTRIDE * 2) + q * 16;
        wdst[i] = ABUF_B + row * (ASTRIDE * 2) + q * 16;
    }

    float acc[4][4][4];
#pragma unroll
    for (int a = 0; a < 4; a++)
#pragma unroll
        for (int b = 0; b < 4; b++)
#pragma unroll
            for (int c = 0; c < 4; c++) acc[a][b][c] = 0.f;

    const int frow = lane & 15, fk = (lane >> 4) * 8;
    uint32_t offA[4], offB[2];
#pragma unroll
    for (int mf = 0; mf < 4; mf++)
        offA[mf] = ((warpM * 64 + mf * 16 + frow) * ASTRIDE + fk) * 2;
#pragma unroll
    for (int nb = 0; nb < 2; nb++)
        offB[nb] = ((warpN * 32 + nb * 16 + frow) * ASTRIDE + fk) * 2;

    const int nch = K / BK;

    // ---- prologue: issue stages 0,1 (groups 0,1) ----
#pragma unroll
    for (int pc = 0; pc < 2; pc++) {
        uint32_t sb = sbase + pc * STAGE_B;
        int koff = pc * BK;
#pragma unroll
        for (int i = 0; i < 2; i++) {
            cp16(sb + adst[i], asrc[i] + koff);
            cp16(sb + wdst[i], wsrc[i] + koff);
        }
        CP_COMMIT();
    }

    for (int c = 0; c < nch; c++) {
        // groups committed so far = c + 2; wait ≤1 pending => group c complete
        CP_WAIT1();
        __syncthreads();   // all warps' slices of stage c visible; stage c-1 retired

        if (c + 2 < nch) {
            uint32_t sb = sbase + ((c + 2) % NSTAGE) * STAGE_B;
            int koff = (c + 2) * BK;
#pragma unroll
            for (int i = 0; i < 2; i++) {
                cp16(sb + adst[i], asrc[i] + koff);
                cp16(sb + wdst[i], wsrc[i] + koff);
            }
            CP_COMMIT();
        } else {
            CP_COMMIT();   // empty group keeps the wait accounting uniform
        }

        uint32_t bufA = sbase + (c % NSTAGE) * STAGE_B;
        uint32_t bufW = bufA + ABUF_B;
#pragma unroll
        for (int ks = 0; ks < 2; ks++) {
            uint32_t ar[4][4], bw[2][4];
#pragma unroll
            for (int mf = 0; mf < 4; mf++)
                ldmx4(ar[mf], bufA + offA[mf] + ks * 32);
#pragma unroll
            for (int nb = 0; nb < 2; nb++)
                ldmx4(bw[nb], bufW + offB[nb] + ks * 32);
#pragma unroll
            for (int mf = 0; mf < 4; mf++) {
#pragma unroll
                for (int nf = 0; nf < 4; nf++) {
                    int nb = nf >> 1, sel = nf & 1;
                    mma_f16(acc[mf][nf], ar[mf], bw[nb][sel], bw[nb][sel + 2]);
                }
            }
        }
        // no trailing sync: next iteration's leading sync provides the barrier
    }

    // ---- epilogue ----
    const int g = lane >> 2, tig = lane & 3;
    float bj0[4], bj1[4], sj0[4], sj1[4], tj0[4], tj1[4];
#pragma unroll
    for (int nf = 0; nf < 4; nf++) {
        int col = colBase + warpN * 32 + nf * 8 + 2 * tig;
        bj0[nf] = bias[col];
        bj1[nf] = bias[col + 1];
        if (bns) {
            sj0[nf] = bns[col];  sj1[nf] = bns[col + 1];
            tj0[nf] = bnt[col];  tj1[nf] = bnt[col + 1];
        }
    }
#pragma unroll
    for (int mf = 0; mf < 4; mf++)
#pragma unroll
        for (int nf = 0; nf < 4; nf++)
#pragma unroll
            for (int half = 0; half < 2; half++) {
                float v0 = acc[mf][nf][half * 2 + 0] + bj0[nf];
                float v1 = acc[mf][nf][half * 2 + 1] + bj1[nf];
                if (bns) {
                    v0 = fmaf(v0, sj0[nf], tj0[nf]);
                    v1 = fmaf(v1, sj1[nf], tj1[nf]);
                }
                if (relu) { v0 = fmaxf(v0, 0.f); v1 = fmaxf(v1, 0.f); }
                acc[mf][nf][half * 2 + 0] = v0;
                acc[mf][nf][half * 2 + 1] = v1;
            }

    if (dosm) {
        __syncthreads();   // retire pipeline smem reads before smax/ssum reuse
        float rowmax[4][2];
#pragma unroll
        for (int mf = 0; mf < 4; mf++)
#pragma unroll
            for (int half = 0; half < 2; half++) {
                float mx = -1e30f;
#pragma unroll
                for (int nf = 0; nf < 4; nf++) {
                    mx = fmaxf(mx, acc[mf][nf][half * 2 + 0]);
                    mx = fmaxf(mx, acc[mf][nf][half * 2 + 1]);
                }
                mx = fmaxf(mx, __shfl_xor_sync(0xffffffffu, mx, 1));
                mx = fmaxf(mx, __shfl_xor_sync(0xffffffffu, mx, 2));
                int row = warpM * 64 + mf * 16 + g + half * 8;
                if (tig == 0) smax[row][warpN] = mx;
            }
        __syncthreads();
#pragma unroll
        for (int mf = 0; mf < 4; mf++)
#pragma unroll
            for (int half = 0; half < 2; half++) {
                int row = warpM * 64 + mf * 16 + g + half * 8;
                float mx = fmaxf(fmaxf(smax[row][0], smax[row][1]),
                                 fmaxf(smax[row][2], smax[row][3]));
                rowmax[mf][half] = mx;
                float se = 0.f;
#pragma unroll
                for (int nf = 0; nf < 4; nf++) {
                    se += expf(acc[mf][nf][half * 2 + 0] - mx);
                    se += expf(acc[mf][nf][half * 2 + 1] - mx);
                }
                se += __shfl_xor_sync(0xffffffffu, se, 1);
                se += __shfl_xor_sync(0xffffffffu, se, 2);
                if (tig == 0) ssum[row][warpN] = se;
            }
        __syncthreads();
#pragma unroll
        for (int mf = 0; mf < 4; mf++)
#pragma unroll
            for (int half = 0; half < 2; half++) {
                int row = warpM * 64 + mf * 16 + g + half * 8;
                int grow = rowBase + row;
                if (grow >= M) continue;
                float tot = ssum[row][0] + ssum[row][1] + ssum[row][2] + ssum[row][3];
                float lse = rowmax[mf][half] + logf(tot);
#pragma unroll
                for (int nf = 0; nf < 4; nf++) {
                    int col = colBase + warpN * 32 + nf * 8 + 2 * tig;
                    float2 o = make_float2(acc[mf][nf][half * 2 + 0] - lse,
                                           acc[mf][nf][half * 2 + 1] - lse);
                    *(float2*)(Cf + (size_t)grow * Nc + col) = o;
                }
            }
        return;
    }

#pragma unroll
    for (int mf = 0; mf < 4; mf++)
#pragma unroll
        for (int half = 0; half < 2; half++) {
            int row = rowBase + warpM * 64 + mf * 16 + g + half * 8;
            if (row >= M) continue;
#pragma unroll
            for (int nf = 0; nf < 4; nf++) {
                int col = colBase + warpN * 32 + nf * 8 + 2 * tig;
                float v0 = acc[mf][nf][half * 2 + 0];
                float v1 = acc[mf][nf][half * 2 + 1];
                if (Cf) {
                    *(float2*)(Cf + (size_t)row * Nc + col) = make_float2(v0, v1);
                } else {
                    __half2 p = __floats2half2_rn(v0, v1);
                    *(uint32_t*)(Ch + (size_t)row * Nc + col) = *(uint32_t*)&p;
                }
            }
        }
}

// ---------------------------------------------------------------------------
extern "C" void kernel_launch(void* const* d_in, const int* in_sizes, int n_in,
                              void* d_out, int out_size)
{
    const float* x    = (const float*)d_in[0];
    const int*   ei   = (const int*)  d_in[1];
    const float* W1   = (const float*)d_in[2];
    const float* b1   = (const float*)d_in[3];
    const float* g1   = (const float*)d_in[4];
    const float* be1  = (const float*)d_in[5];
    const float* m1   = (const float*)d_in[6];
    const float* v1   = (const float*)d_in[7];
    const float* W2   = (const float*)d_in[8];
    const float* b2   = (const float*)d_in[9];
    const float* eps  = (const float*)d_in[10];
    const float* go   = (const float*)d_in[11];
    const float* bo   = (const float*)d_in[12];
    const float* mo   = (const float*)d_in[13];
    const float* vo   = (const float*)d_in[14];

    int N = in_sizes[0] / DIM;
    int E = in_sizes[1] / 2;

    float *s1, *t1, *so, *to;
    __half *hh, *cb, *zb, *w1, *w2;
    int *rowptr, *cursor, *adj, *part;
    cudaGetSymbolAddress((void**)&hh,     g_hh);
    cudaGetSymbolAddress((void**)&cb,     g_c);
    cudaGetSymbolAddress((void**)&zb,     g_z);
    cudaGetSymbolAddress((void**)&s1,     g_s1);
    cudaGetSymbolAddress((void**)&t1,     g_t1);
    cudaGetSymbolAddress((void**)&so,     g_so);
    cudaGetSymbolAddress((void**)&to,     g_to);
    cudaGetSymbolAddress((void**)&w1,     g_w1);
    cudaGetSymbolAddress((void**)&w2,     g_w2);
    cudaGetSymbolAddress((void**)&rowptr, g_rowptr);
    cudaGetSymbolAddress((void**)&cursor, g_cursor);
    cudaGetSymbolAddress((void**)&adj,    g_adj);
    cudaGetSymbolAddress((void**)&part,   g_part);

    const int dynSmem = NSTAGE * STAGE_B;  // 61440 B
    cudaFuncSetAttribute(gemm_mma_kernel, cudaFuncAttributeMaxDynamicSharedMemorySize, dynSmem);

    const int* src = ei;
    const int* dst = ei + E;

    // ---- setup: one fused kernel + memset + CSR build ----
    int nx2  = N * DIM / 2;
    int wtot = LNUM * 2 * DIM * DIM;
    int smax_work = nx2 > wtot ? nx2 : wtot;
    setup_kernel<<<(smax_work + 255) / 256, 256>>>(x, hh, nx2, W1, W2, w1, w2, wtot,
                                                   g1, be1, m1, v1, go, bo, mo, vo,
                                                   s1, t1, so, to);
    int n1 = N + 1;
    int sblocks = (n1 + 1023) / 1024;
    cudaMemsetAsync(rowptr, 0, (size_t)n1 * sizeof(int));
    hist_kernel<<<(E + 255) / 256, 256>>>(dst, rowptr, E);
    scan1_kernel<<<sblocks, 1024>>>(rowptr, part, n1);
    scan2_kernel<<<1, 64>>>(part, sblocks);
    scan3_kernel<<<sblocks, 1024>>>(rowptr, part, cursor, n1);
    fill_kernel<<<(E + 255) / 256, 256>>>(src, dst, cursor, adj, E);

    int mblocks = (N + 127) / 128;
    int gblocks = (N + 7) / 8;

    for (int i = 0; i < LNUM; i++) {
        gather_kernel<<<gblocks, 256>>>(hh, rowptr, adj, eps + i, cb, N);

        dim3 grid1(2, mblocks);
        gemm_mma_kernel<<<grid1, 256, dynSmem>>>(cb,
                                                 w1 + (size_t)i * 2 * DIM * DIM,
                                                 b1 + (size_t)i * 2 * DIM,
                                                 s1 + (size_t)i * 2 * DIM,
                                                 t1 + (size_t)i * 2 * DIM,
                                                 nullptr, zb,
                                                 N, DIM, 2 * DIM, 1, 0);

        dim3 grid2(1, mblocks);
        if (i < LNUM - 1) {
            gemm_mma_kernel<<<grid2, 256, dynSmem>>>(zb,
                                                     w2 + (size_t)i * 2 * DIM * DIM,
                                                     b2 + (size_t)i * DIM,
                                                     so + (size_t)i * DIM,
                                                     to + (size_t)i * DIM,
                                                     nullptr, hh,
                                                     N, 2 * DIM, DIM, 1, 0);
        } else {
            gemm_mma_kernel<<<grid2, 256, dynSmem>>>(zb,
                                                     w2 + (size_t)i * 2 * DIM * DIM,
                                                     b2 + (size_t)i * DIM,
                                                     nullptr, nullptr,
                                                     (float*)d_out, nullptr,
                                                     N, 2 * DIM, DIM, 0, 1);
        }
    }
}